// round 12
// baseline (speedup 1.0000x reference)
#include <cuda_runtime.h>
#include <math.h>

#define BATCH 4
#define SEQ   2048
#define DIM   128
#define ROWS  (BATCH*SEQ)   // 8192

typedef unsigned long long ull;
typedef unsigned int uint32;

// ---------------- scratch (no allocation allowed) ----------------
__device__ float g_xr[ROWS*DIM];      // rna tf32-rounded x
__device__ float g_wr[DIM*(3*DIM+2*DIM)];  // rna tf32 Wq|Wk|Wv|Wu (offsets 0,16384,32768,49152)
__device__ float g_q[ROWS*DIM];       // tf32-rounded, PRE-SCALED by 1/sqrt(32)
__device__ float g_k[ROWS*DIM];
__device__ float g_vt[ROWS*DIM];      // TRANSPOSED: [b][d=128][token=2048]
__device__ float g_u[ROWS*2*DIM];     // full f32
__device__ float g_wf[2*DIM*DIM];     // rna tf32 Wf
__device__ float g_sattn[ROWS*DIM];
__device__ float g_pattn[ROWS*DIM];

__device__ __forceinline__ float silu_f(float v) {
    return v * (1.f / (1.f + __expf(-v)));
}
__device__ __forceinline__ float tanh_ap(float x) {
    float y; asm("tanh.approx.f32 %0, %1;" : "=f"(y) : "f"(x)); return y;
}
__device__ __forceinline__ float silu_t(float x) {
    return fmaf(x, 0.5f * tanh_ap(0.5f * x), 0.5f * x);
}
__device__ __forceinline__ uint32 tf32_of(float f) {
    uint32 u; asm("cvt.rna.tf32.f32 %0, %1;" : "=r"(u) : "f"(f)); return u;
}
__device__ __forceinline__ float tf32f(float f) { return __uint_as_float(tf32_of(f)); }
__device__ __forceinline__ uint32 fb(float f) { return __float_as_uint(f); }
__device__ __forceinline__ uint32 smem_u32(const void* p) {
    return (uint32)__cvta_generic_to_shared(p);
}

__device__ __forceinline__ void mma_tf32(float4& d, uint32 a0, uint32 a1, uint32 a2, uint32 a3,
                                         uint32 b0, uint32 b1) {
    asm volatile(
        "mma.sync.aligned.m16n8k8.row.col.f32.tf32.tf32.f32 "
        "{%0,%1,%2,%3}, {%4,%5,%6,%7}, {%8,%9}, {%0,%1,%2,%3};"
        : "+f"(d.x), "+f"(d.y), "+f"(d.z), "+f"(d.w)
        : "r"(a0), "r"(a1), "r"(a2), "r"(a3), "r"(b0), "r"(b1));
}
__device__ __forceinline__ void ldsm_x4(uint32& r0, uint32& r1, uint32& r2, uint32& r3, uint32 addr) {
    asm volatile("ldmatrix.sync.aligned.m8n8.x4.shared.b16 {%0,%1,%2,%3}, [%4];"
        : "=r"(r0), "=r"(r1), "=r"(r2), "=r"(r3) : "r"(addr));
}
__device__ __forceinline__ void ldsm_x2(uint32& r0, uint32& r1, uint32 addr) {
    asm volatile("ldmatrix.sync.aligned.m8n8.x2.shared.b16 {%0,%1}, [%2];"
        : "=r"(r0), "=r"(r1) : "r"(addr));
}
__device__ __forceinline__ void cp16(uint32 dst, const float* src) {
    asm volatile("cp.async.ca.shared.global [%0], [%1], 16;" :: "r"(dst), "l"(src));
}
#define CP_COMMIT() asm volatile("cp.async.commit_group;")
#define CP_WAIT2()  asm volatile("cp.async.wait_group 2;")
#define CP_WAIT1()  asm volatile("cp.async.wait_group 1;")
#define CP_WAIT0()  asm volatile("cp.async.wait_group 0;")

// ---------------- kernel 0: rna tf32 pre-rounding of x and all weights ----------------
// grid 1136 x 256: x 1024 | Wq 16 | Wk 16 | Wv 16 | Wu 32 | Wf 32 blocks (1 float4/thread)
__global__ __launch_bounds__(256) void round_kernel(
    const float* __restrict__ x,
    const float* __restrict__ Wq, const float* __restrict__ Wk,
    const float* __restrict__ Wv, const float* __restrict__ Wu,
    const float* __restrict__ Wf)
{
    const int b = blockIdx.x, t = threadIdx.x;
    const float* src; float* dst; int i4;
    if (b < 1024)      { src = x;  dst = g_xr;          i4 = b*256 + t; }
    else if (b < 1040) { src = Wq; dst = g_wr;          i4 = (b-1024)*256 + t; }
    else if (b < 1056) { src = Wk; dst = g_wr + 16384;  i4 = (b-1040)*256 + t; }
    else if (b < 1072) { src = Wv; dst = g_wr + 32768;  i4 = (b-1056)*256 + t; }
    else if (b < 1104) { src = Wu; dst = g_wr + 49152;  i4 = (b-1072)*256 + t; }
    else               { src = Wf; dst = g_wf;          i4 = (b-1104)*256 + t; }
    float4 v = ((const float4*)src)[i4];
    ((float4*)dst)[i4] = make_float4(tf32f(v.x), tf32f(v.y), tf32f(v.z), tf32f(v.w));
}

// ---------------- kernel 1: fused q/k/v/u projections (tf32 mma, cp.async pipeline) ----------------
// grid (5, 128). seg 0=q(pre-scaled), 1=k, 2=v(transposed), 3/4=u halves. Sources pre-rounded rna.
#define PROJ_SMEM 53248
__global__ __launch_bounds__(256) void proj_kernel(
    const float* __restrict__ bq, const float* __restrict__ bk,
    const float* __restrict__ bv, const float* __restrict__ bu)
{
    extern __shared__ float psm[];
    float (*xs)[36]  = (float(*)[36])psm;                 // 2 x 64 rows
    float (*ws)[136] = (float(*)[136])(psm + 2*64*36);    // 2 x 32 rows

    const int seg = blockIdx.x;
    const int r0  = blockIdx.y * 64;

    const float* W; const float* bias; int ldw, c0;
    if (seg == 0)      { W = g_wr;         bias = bq; ldw = 128; c0 = 0; }
    else if (seg == 1) { W = g_wr + 16384; bias = bk; ldw = 128; c0 = 0; }
    else if (seg == 2) { W = g_wr + 32768; bias = bv; ldw = 128; c0 = 0; }
    else               { W = g_wr + 49152; bias = bu; ldw = 256; c0 = (seg - 3) * 128; }

    const int t = threadIdx.x;
    const int w = t >> 5, lane = t & 31;
    const int wm = w & 3, wn = w >> 2;
    const int g = lane >> 2, tg = lane & 3;

    const int lrow = lane & 7;
    const int sel4 = lane >> 3;
    const int a_ro = ((sel4 & 1) << 3) + lrow;
    const int a_co = (sel4 & 2) ? 4 : 0;

    const uint32 xs_u = smem_u32(&xs[0][0]);
    const uint32 ws_u = smem_u32(&ws[0][0]);
    const float* xp = g_xr + r0 * 128;

    #pragma unroll
    for (int i = t; i < 512; i += 256) {
        int r = i >> 3, q = (i & 7) << 2;
        cp16(xs_u + (r*36 + q)*4, xp + r*128 + q);
    }
    #pragma unroll
    for (int i = t; i < 1024; i += 256) {
        int r = i >> 5, q = (i & 31) << 2;
        cp16(ws_u + (r*136 + q)*4, W + r*ldw + c0 + q);
    }
    CP_COMMIT();

    float4 acc[8];
    #pragma unroll
    for (int j = 0; j < 8; j++) acc[j] = make_float4(0.f, 0.f, 0.f, 0.f);

    const uint32 xa = xs_u + ((wm*16 + a_ro)*36 + a_co)*4;

    #pragma unroll
    for (int kc = 0; kc < 4; kc++) {
        const int buf = kc & 1;
        if (kc < 3) {
            const int nb = buf ^ 1, k1 = (kc + 1) * 32;
            #pragma unroll
            for (int i = t; i < 512; i += 256) {
                int r = i >> 3, q = (i & 7) << 2;
                cp16(xs_u + ((nb*64 + r)*36 + q)*4, xp + r*128 + k1 + q);
            }
            #pragma unroll
            for (int i = t; i < 1024; i += 256) {
                int r = i >> 5, q = (i & 31) << 2;
                cp16(ws_u + ((nb*32 + r)*136 + q)*4, W + (k1 + r)*ldw + c0 + q);
            }
            CP_COMMIT();
            CP_WAIT1();
        } else {
            CP_WAIT0();
        }
        __syncthreads();

        const uint32 xab = xa + (uint32)buf*64*36*4;
        #pragma unroll
        for (int kk = 0; kk < 32; kk += 8) {
            uint32 A[4];
            ldsm_x4(A[0], A[1], A[2], A[3], xab + kk*4);
            #pragma unroll
            for (int j = 0; j < 8; j++) {
                uint32 b0 = fb(ws[buf*32 + kk + tg    ][wn*64 + j*8 + g]);
                uint32 b1 = fb(ws[buf*32 + kk + tg + 4][wn*64 + j*8 + g]);
                mma_tf32(acc[j], A[0], A[1], A[2], A[3], b0, b1);
            }
        }
        __syncthreads();
    }

    if (seg == 2) {
        const int bb = r0 >> 11;
        const int tok = (r0 & 2047) + wm*16 + g;
        #pragma unroll
        for (int j = 0; j < 8; j++) {
            int col = wn*64 + j*8 + 2*tg;
            float b0v = bias[col], b1v = bias[col + 1];
            float v00 = tf32f(silu_f(acc[j].x + b0v));
            float v01 = tf32f(silu_f(acc[j].y + b1v));
            float v10 = tf32f(silu_f(acc[j].z + b0v));
            float v11 = tf32f(silu_f(acc[j].w + b1v));
            float* p0 = &g_vt[(bb*128 + col) * SEQ + tok];
            p0[0] = v00; p0[8] = v10;
            float* p1 = p0 + SEQ;
            p1[0] = v01; p1[8] = v11;
        }
    } else {
        float* out = (seg == 0) ? g_q : (seg == 1) ? g_k : g_u;
        bool act = (seg <= 1);
        const float mult = (seg == 0) ? 0.17677669529663687f : 1.0f;
        #pragma unroll
        for (int j = 0; j < 8; j++) {
            int col = c0 + wn*64 + j*8 + 2*tg;
            float b0v = bias[col], b1v = bias[col + 1];
            int row0 = r0 + wm*16 + g;
            float v00 = acc[j].x + b0v, v01 = acc[j].y + b1v;
            float v10 = acc[j].z + b0v, v11 = acc[j].w + b1v;
            if (act) {
                v00 = tf32f(silu_f(v00) * mult); v01 = tf32f(silu_f(v01) * mult);
                v10 = tf32f(silu_f(v10) * mult); v11 = tf32f(silu_f(v11) * mult);
            }
            *(float2*)&out[row0 * ldw + col]       = make_float2(v00, v01);
            *(float2*)&out[(row0 + 8) * ldw + col] = make_float2(v10, v11);
        }
    }
}

// ---------------- kernel 2: MERGED attn + pos (single wave, 384 blocks) ----------------
// attn: 128-row tiles, 8 warps each m16 x full-n64, P passed stage1->stage2 in registers
// via quad shuffles (no ss smem). smem: qs 128x36 | ks 2x64x36 | vts 2x32x68 = 54272 B
#define AP_SMEM 54272

__device__ __forceinline__ void attn_body(int p, int bh, int t, float* sm)
{
    float (*qs)[36]  = (float(*)[36])sm;                 // 128 rows
    float (*ks)[36]  = (float(*)[36])(sm + 4608);        // 2*64 rows
    float (*vts)[68] = (float(*)[68])(sm + 9216);        // 2*32 rows

    const int b = bh >> 2, h = bh & 3;
    const int w = t >> 5, lane = t & 31;
    const int g = lane >> 2, tg = lane & 3;

    const float* kp  = g_k  + (b*SEQ)*128 + h*32;
    const float* vtp = g_vt + (b*128 + h*32)*SEQ;

    const uint32 qs_u = smem_u32(&qs[0][0]);
    const uint32 ks_u = smem_u32(&ks[0][0]);
    const uint32 vt_u = smem_u32(&vts[0][0]);

    const int lrow = lane & 7;
    const int sel4 = lane >> 3;
    const int a_ro = ((sel4 & 1) << 3) + lrow;
    const int a_co = (sel4 & 2) ? 4 : 0;
    const int l16  = lane & 15;
    const int b_ro = l16 & 7;
    const int b_co = (l16 >> 3) << 2;

    const uint32 qa = qs_u + ((w*16 + a_ro)*36 + a_co)*4;
    const int src0 = (lane & ~3) | (tg >> 1);
    const int src1 = src0 + 2;
    const bool odd = tg & 1;

    #pragma unroll
    for (int ph = 0; ph < 2; ph++) {
        const int tile = ph ? p : 15 - p;        // long phase first
        const int n0 = tile * 128;
        const float* qp = g_q + (b*SEQ + n0)*128 + h*32;

        // q tile: 128 rows x 32 floats = 1024 float4
        #pragma unroll
        for (int c = t; c < 1024; c += 256) {
            int r = c >> 3, s = (c & 7) << 2;
            cp16(qs_u + (r*36 + s)*4, qp + r*128 + s);
        }
        // first k/vt tile
        #pragma unroll
        for (int c = t; c < 512; c += 256) {
            int r = c >> 3, s = (c & 7) << 2;
            cp16(ks_u + (r*36 + s)*4, kp + r*128 + s);
        }
        #pragma unroll
        for (int c = t; c < 512; c += 256) {
            int r = c >> 4, s = (c & 15) << 2;
            cp16(vt_u + (r*68 + s)*4, vtp + r*SEQ + s);
        }
        CP_COMMIT();

        float4 acc[4];
        #pragma unroll
        for (int j = 0; j < 4; j++) acc[j] = make_float4(0.f, 0.f, 0.f, 0.f);

        const int iters = 2*tile + 2;
        for (int it = 0; it < iters; ++it) {
            const int m0 = it * 64;
            const int buf = it & 1;
            if (it + 1 < iters) {
                const int m1 = m0 + 64, nb = buf ^ 1;
                #pragma unroll
                for (int c = t; c < 512; c += 256) {
                    int r = c >> 3, s = (c & 7) << 2;
                    cp16(ks_u + ((nb*64 + r)*36 + s)*4, kp + (m1 + r)*128 + s);
                }
                #pragma unroll
                for (int c = t; c < 512; c += 256) {
                    int r = c >> 4, s = (c & 15) << 2;
                    cp16(vt_u + ((nb*32 + r)*68 + s)*4, vtp + r*SEQ + m1 + s);
                }
                CP_COMMIT();
                CP_WAIT1();
            } else {
                CP_WAIT0();
            }
            __syncthreads();

            // ---- stage 1: scores (warp m16 x n64)
            float4 sc[8];
            #pragma unroll
            for (int j = 0; j < 8; j++) sc[j] = make_float4(0.f, 0.f, 0.f, 0.f);

            const uint32 kb = ks_u + (uint32)buf*64*36*4 + (b_ro*36 + b_co)*4;
            #pragma unroll
            for (int kk = 0; kk < 32; kk += 8) {
                uint32 A[4];
                ldsm_x4(A[0], A[1], A[2], A[3], qa + kk*4);
                #pragma unroll
                for (int j = 0; j < 8; j++) {
                    uint32 b0, b1;
                    ldsm_x2(b0, b1, kb + (j*8*36 + kk)*4);
                    mma_tf32(sc[j], A[0], A[1], A[2], A[3], b0, b1);
                }
            }

            // ---- mask + square + silu(tanh), keep P in registers (tf32 rna)
            {
                const int nrow0 = n0 + w*16 + g, nrow1 = nrow0 + 8;
                #pragma unroll
                for (int j = 0; j < 8; j++) {
                    const int cc = m0 + j*8 + 2*tg;
                    float s;
                    s = sc[j].x; s = (cc     <= nrow0) ? s*s : 0.f; sc[j].x = tf32f(silu_t(s));
                    s = sc[j].y; s = (cc + 1 <= nrow0) ? s*s : 0.f; sc[j].y = tf32f(silu_t(s));
                    s = sc[j].z; s = (cc     <= nrow1) ? s*s : 0.f; sc[j].z = tf32f(silu_t(s));
                    s = sc[j].w; s = (cc + 1 <= nrow1) ? s*s : 0.f; sc[j].w = tf32f(silu_t(s));
                }
            }

            // ---- stage 2: acc += P @ V ; A-fragments via quad shuffles from sc
            const uint32 vb = vt_u + (uint32)buf*32*68*4 + (b_ro*68 + b_co)*4;
            #pragma unroll
            for (int kchunk = 0; kchunk < 8; kchunk++) {
                float4 s = sc[kchunk];
                float x0 = __shfl_sync(0xffffffffu, s.x, src0);
                float y0 = __shfl_sync(0xffffffffu, s.y, src0);
                float z0 = __shfl_sync(0xffffffffu, s.z, src0);
                float w0 = __shfl_sync(0xffffffffu, s.w, src0);
                float x1 = __shfl_sync(0xffffffffu, s.x, src1);
                float y1 = __shfl_sync(0xffffffffu, s.y, src1);
                float z1 = __shfl_sync(0xffffffffu, s.z, src1);
                float w1 = __shfl_sync(0xffffffffu, s.w, src1);
                uint32 a0 = fb(odd ? y0 : x0);
                uint32 a1 = fb(odd ? w0 : z0);
                uint32 a2 = fb(odd ? y1 : x1);
                uint32 a3 = fb(odd ? w1 : z1);
                #pragma unroll
                for (int j = 0; j < 4; j++) {
                    uint32 b0, b1;
                    ldsm_x2(b0, b1, vb + (j*8*68 + kchunk*8)*4);
                    mma_tf32(acc[j], a0, a1, a2, a3, b0, b1);
                }
            }
            __syncthreads();
        }

        {
            const int row0 = n0 + w*16 + g;
            #pragma unroll
            for (int j = 0; j < 4; j++) {
                const int col = h*32 + j*8 + 2*tg;
                *(float2*)&g_sattn[(b*SEQ + row0    )*128 + col] = make_float2(acc[j].x, acc[j].y);
                *(float2*)&g_sattn[(b*SEQ + row0 + 8)*128 + col] = make_float2(acc[j].z, acc[j].w);
            }
        }
    }
}

__device__ __forceinline__ void pos_body(int idx, int t, float* sm, const float* __restrict__ pos_w)
{
    float* swl = sm;                                   // 4096 (tf32-rounded pos_w)
    float (*vts)[68] = (float(*)[68])(sm + 4096);      // 2*64 rows

    const int n0 = (idx & 31) * 64;
    const int d0 = ((idx >> 5) & 1) * 64;
    const int b  = idx >> 6;
    const int w = t >> 5, lane = t & 31;
    const int wmn = w & 1, wd = w >> 1;
    const int g = lane >> 2, tg = lane & 3;

    const int l16  = lane & 15;
    const int b_ro = l16 & 7;
    const int b_co = (l16 >> 3) << 2;

    const uint32 vt_u = smem_u32(&vts[0][0]);
    const float* vtp = g_vt + (b*128 + d0)*SEQ;

    for (int i = t; i < 4095; i += 256) swl[i] = tf32f(pos_w[i]);
    if (t == 0) swl[4095] = 0.f;

    #pragma unroll
    for (int c = t; c < 1024; c += 256) {
        int r = c >> 4, s = (c & 15) << 2;
        cp16(vt_u + (r*68 + s)*4, vtp + r*SEQ + s);
    }
    CP_COMMIT();

    float4 acc[2][2];
    #pragma unroll
    for (int mi = 0; mi < 2; mi++)
        #pragma unroll
        for (int j = 0; j < 2; j++) acc[mi][j] = make_float4(0.f, 0.f, 0.f, 0.f);

    const int abase = 2047 - n0 - wmn*32 - g + tg;

    for (int it = 0; it < 32; ++it) {
        const int m0 = it * 64;
        const int buf = it & 1;
        if (it < 31) {
            const int m1 = m0 + 64, nb = buf ^ 1;
            #pragma unroll
            for (int c = t; c < 1024; c += 256) {
                int r = c >> 4, s = (c & 15) << 2;
                cp16(vt_u + ((nb*64 + r)*68 + s)*4, vtp + r*SEQ + m1 + s);
            }
            CP_COMMIT();
            CP_WAIT1();
        } else {
            CP_WAIT0();
        }
        __syncthreads();

        const uint32 vb = vt_u + (uint32)buf*64*68*4 + ((wd*16 + b_ro)*68 + b_co)*4;
        const float* ab = swl + abase + m0;
        #pragma unroll
        for (int kk = 0; kk < 64; kk += 8) {
            uint32 A0[4], A1[4];
            {
                const float* pp = ab + kk;
                A0[0] = fb(pp[0]);   A0[1] = fb(pp[-8]);
                A0[2] = fb(pp[4]);   A0[3] = fb(pp[-4]);
                const float* qq = pp - 16;
                A1[0] = fb(qq[0]);   A1[1] = fb(qq[-8]);
                A1[2] = fb(qq[4]);   A1[3] = fb(qq[-4]);
            }
            #pragma unroll
            for (int j = 0; j < 2; j++) {
                uint32 b0, b1;
                ldsm_x2(b0, b1, vb + (j*8*68 + kk)*4);
                mma_tf32(acc[0][j], A0[0], A0[1], A0[2], A0[3], b0, b1);
                mma_tf32(acc[1][j], A1[0], A1[1], A1[2], A1[3], b0, b1);
            }
        }
        __syncthreads();
    }

    #pragma unroll
    for (int mi = 0; mi < 2; mi++) {
        const int row0 = n0 + wmn*32 + mi*16 + g;
        #pragma unroll
        for (int j = 0; j < 2; j++) {
            const int col = d0 + wd*16 + j*8 + 2*tg;
            *(float2*)&g_pattn[(b*SEQ + row0    )*128 + col] = make_float2(acc[mi][j].x, acc[mi][j].y);
            *(float2*)&g_pattn[(b*SEQ + row0 + 8)*128 + col] = make_float2(acc[mi][j].z, acc[mi][j].w);
        }
    }
}

__global__ __launch_bounds__(256, 3) void attnpos_kernel(const float* __restrict__ pos_w)
{
    extern __shared__ float sm[];
    const int bx = blockIdx.x;
    const int q3 = bx / 3, r3 = bx - q3 * 3;
    if (r3 == 0) {
        // attn: 128 blocks; p = pair id (0..7), bh (0..15)
        attn_body(q3 & 7, q3 >> 3, threadIdx.x, sm);
    } else {
        // pos: 256 blocks
        pos_body(q3 * 2 + (r3 - 1), threadIdx.x, sm, pos_w);
    }
}

// ---------------- kernel 3: fused LN + final GEMM (tf32 mma, pipelined Wf) ----------------
#define FIN_SMEM 67072
__global__ __launch_bounds__(256) void final_kernel(const float* __restrict__ x,
                                                    const float* __restrict__ bf,
                                                    const float* __restrict__ gamma,
                                                    const float* __restrict__ beta,
                                                    float* __restrict__ out)
{
    extern __shared__ float sm[];
    float (*as)[260] = (float(*)[260])sm;
    float (*ws)[132] = (float(*)[132])(sm + 32*260);

    const int r0 = blockIdx.x * 32;
    const int t  = threadIdx.x;
    const uint32 as_u = smem_u32(&as[0][0]);
    const uint32 ws_u = smem_u32(&ws[0][0]);

    #pragma unroll
    for (int i = t; i < 2048; i += 256) {
        int r = i >> 6, c4 = i & 63;
        const float* src = (c4 < 32) ? &g_sattn[(r0 + r)*128 + c4*4]
                                     : &g_pattn[(r0 + r)*128 + (c4 - 32)*4];
        cp16(as_u + (r*260 + c4*4)*4, src);
    }
    CP_COMMIT();
    #pragma unroll
    for (int i = t; i < 1024; i += 256) {
        int r = i >> 5, c4 = i & 31;
        cp16(ws_u + (r*132 + c4*4)*4, &g_wf[r*128 + c4*4]);
    }
    CP_COMMIT();
    #pragma unroll
    for (int i = t; i < 1024; i += 256) {
        int r = i >> 5, c4 = i & 31;
        cp16(ws_u + ((32 + r)*132 + c4*4)*4, &g_wf[(32 + r)*128 + c4*4]);
    }
    CP_COMMIT();
    CP_WAIT2();
    __syncthreads();

    {
        const int r = t >> 3, sub = t & 7;
        float vals[32];
        #pragma unroll
        for (int k4 = 0; k4 < 8; k4++) {
            float4 v = *(const float4*)&as[r][sub*4 + k4*32];
            vals[k4*4+0] = v.x; vals[k4*4+1] = v.y; vals[k4*4+2] = v.z; vals[k4*4+3] = v.w;
        }
        float sum = 0.f, sq = 0.f;
        #pragma unroll
        for (int k = 0; k < 32; k++) { sum += vals[k]; sq = fmaf(vals[k], vals[k], sq); }
        #pragma unroll
        for (int o = 1; o < 8; o <<= 1) {
            sum += __shfl_xor_sync(0xffffffffu, sum, o);
            sq  += __shfl_xor_sync(0xffffffffu, sq, o);
        }
        const float mean = sum * (1.f / 256.f);
        const float var  = sq * (1.f / 256.f) - mean * mean;
        const float rstd = rsqrtf(var + 1e-3f);

        #pragma unroll
        for (int k4 = 0; k4 < 8; k4++) {
            const int c = sub*4 + k4*32;
            float4 ga = *(const float4*)&gamma[c];
            float4 be = *(const float4*)&beta[c];
            float4 uu = *(const float4*)&g_u[(r0 + r)*256 + c];
            float4 o;
            o.x = tf32f(uu.x * ((vals[k4*4+0] - mean) * rstd * ga.x + be.x));
            o.y = tf32f(uu.y * ((vals[k4*4+1] - mean) * rstd * ga.y + be.y));
            o.z = tf32f(uu.z * ((vals[k4*4+2] - mean) * rstd * ga.z + be.z));
            o.w = tf32f(uu.w * ((vals[k4*4+3] - mean) * rstd * ga.w + be.w));
            *(float4*)&as[r][c] = o;
        }
    }
    __syncthreads();

    const int w = t >> 5, lane = t & 31;
    const int wm = w & 1, wn = w >> 1;
    const int g = lane >> 2, tg = lane & 3;
    const int lrow = lane & 7;
    const int sel4 = lane >> 3;
    const int a_ro = ((sel4 & 1) << 3) + lrow;
    const int a_co = (sel4 & 2) ? 4 : 0;

    const uint32 aa = as_u + ((wm*16 + a_ro)*260 + a_co)*4;

    float4 acc[4];
    #pragma unroll
    for (int j = 0; j < 4; j++) acc[j] = make_float4(0.f, 0.f, 0.f, 0.f);

    #pragma unroll
    for (int kchunk = 0; kchunk < 8; kchunk++) {
        const int buf = kchunk & 1;
        CP_WAIT1();
        __syncthreads();

        #pragma unroll
        for (int kk = 0; kk < 32; kk += 8) {
            uint32 A[4];
            ldsm_x4(A[0], A[1], A[2], A[3], aa + (kchunk*32 + kk)*4);
            #pragma unroll
            for (int j = 0; j < 4; j++) {
                uint32 b0 = fb(ws[buf*32 + kk + tg    ][wn*32 + j*8 + g]);
                uint32 b1 = fb(ws[buf*32 + kk + tg + 4][wn*32 + j*8 + g]);
                mma_tf32(acc[j], A[0], A[1], A[2], A[3], b0, b1);
            }
        }
        __syncthreads();

        if (kchunk + 2 < 8) {
            #pragma unroll
            for (int i = t; i < 1024; i += 256) {
                int r = i >> 5, c4 = i & 31;
                cp16(ws_u + ((buf*32 + r)*132 + c4*4)*4,
                     &g_wf[((kchunk + 2)*32 + r)*128 + c4*4]);
            }
        }
        CP_COMMIT();
    }

    {
        const int row0 = r0 + wm*16 + g, row1 = row0 + 8;
        #pragma unroll
        for (int j = 0; j < 4; j++) {
            const int col = wn*32 + j*8 + 2*tg;
            float b0v = bf[col], b1v = bf[col + 1];
            float2 x0 = *(const float2*)&x[row0*128 + col];
            float2 x1 = *(const float2*)&x[row1*128 + col];
            float2 o0, o1;
            o0.x = fmaxf(acc[j].x + b0v, 0.f) + x0.x;
            o0.y = fmaxf(acc[j].y + b1v, 0.f) + x0.y;
            o1.x = fmaxf(acc[j].z + b0v, 0.f) + x1.x;
            o1.y = fmaxf(acc[j].w + b1v, 0.f) + x1.y;
            *(float2*)&out[row0*128 + col] = o0;
            *(float2*)&out[row1*128 + col] = o1;
        }
    }
}

// ---------------- launcher ----------------
extern "C" void kernel_launch(void* const* d_in, const int* in_sizes, int n_in,
                              void* d_out, int out_size)
{
    const float* x      = (const float*)d_in[0];
    const float* Wq     = (const float*)d_in[1];
    const float* bq     = (const float*)d_in[2];
    const float* Wk     = (const float*)d_in[3];
    const float* bk     = (const float*)d_in[4];
    const float* Wv     = (const float*)d_in[5];
    const float* bv     = (const float*)d_in[6];
    const float* Wu     = (const float*)d_in[7];
    const float* bu     = (const float*)d_in[8];
    const float* pos_w  = (const float*)d_in[9];
    const float* gamma  = (const float*)d_in[10];
    const float* beta   = (const float*)d_in[11];
    const float* Wf     = (const float*)d_in[12];
    const float* bf     = (const float*)d_in[13];
    float* out = (float*)d_out;

    cudaFuncSetAttribute(proj_kernel,    cudaFuncAttributeMaxDynamicSharedMemorySize, PROJ_SMEM);
    cudaFuncSetAttribute(attnpos_kernel, cudaFuncAttributeMaxDynamicSharedMemorySize, AP_SMEM);
    cudaFuncSetAttribute(final_kernel,   cudaFuncAttributeMaxDynamicSharedMemorySize, FIN_SMEM);

    round_kernel<<<1136, 256>>>(x, Wq, Wk, Wv, Wu, Wf);
    proj_kernel<<<dim3(5, ROWS/64), 256, PROJ_SMEM>>>(bq, bk, bv, bu);
    attnpos_kernel<<<384, 256, AP_SMEM>>>(pos_w);
    final_kernel<<<ROWS/32, 256, FIN_SMEM>>>(x, bf, gamma, beta, out);
}

// round 13
// speedup vs baseline: 1.1177x; 1.1177x over previous
#include <cuda_runtime.h>
#include <math.h>

#define BATCH 4
#define SEQ   2048
#define DIM   128
#define ROWS  (BATCH*SEQ)   // 8192

typedef unsigned long long ull;
typedef unsigned int uint32;

// ---------------- scratch (no allocation allowed) ----------------
__device__ float g_xr[ROWS*DIM];           // rna tf32-rounded x
__device__ float g_wr[DIM*(3*DIM+2*DIM)];  // rna tf32 Wq|Wk|Wv|Wu
__device__ float g_q[ROWS*DIM];            // tf32, PRE-SCALED by 1/sqrt(32)
__device__ float g_k[ROWS*DIM];
__device__ float g_vt[ROWS*DIM];           // TRANSPOSED: [b][d=128][token=2048]
__device__ float g_u[ROWS*2*DIM];          // full f32
__device__ float g_wf[2*DIM*DIM];          // rna tf32 Wf
__device__ float g_sattn[ROWS*DIM];
__device__ float g_pattn[ROWS*DIM];

__device__ __forceinline__ float silu_f(float v) {
    return v * (1.f / (1.f + __expf(-v)));
}
__device__ __forceinline__ float tanh_ap(float x) {
    float y; asm("tanh.approx.f32 %0, %1;" : "=f"(y) : "f"(x)); return y;
}
__device__ __forceinline__ float silu_t(float x) {
    return fmaf(x, 0.5f * tanh_ap(0.5f * x), 0.5f * x);
}
__device__ __forceinline__ uint32 tf32_of(float f) {
    uint32 u; asm("cvt.rna.tf32.f32 %0, %1;" : "=r"(u) : "f"(f)); return u;
}
__device__ __forceinline__ float tf32f(float f) { return __uint_as_float(tf32_of(f)); }
__device__ __forceinline__ uint32 fb(float f) { return __float_as_uint(f); }
__device__ __forceinline__ uint32 smem_u32(const void* p) {
    return (uint32)__cvta_generic_to_shared(p);
}

__device__ __forceinline__ void mma_tf32(float4& d, uint32 a0, uint32 a1, uint32 a2, uint32 a3,
                                         uint32 b0, uint32 b1) {
    asm volatile(
        "mma.sync.aligned.m16n8k8.row.col.f32.tf32.tf32.f32 "
        "{%0,%1,%2,%3}, {%4,%5,%6,%7}, {%8,%9}, {%0,%1,%2,%3};"
        : "+f"(d.x), "+f"(d.y), "+f"(d.z), "+f"(d.w)
        : "r"(a0), "r"(a1), "r"(a2), "r"(a3), "r"(b0), "r"(b1));
}
__device__ __forceinline__ void ldsm_x4(uint32& r0, uint32& r1, uint32& r2, uint32& r3, uint32 addr) {
    asm volatile("ldmatrix.sync.aligned.m8n8.x4.shared.b16 {%0,%1,%2,%3}, [%4];"
        : "=r"(r0), "=r"(r1), "=r"(r2), "=r"(r3) : "r"(addr));
}
__device__ __forceinline__ void ldsm_x2(uint32& r0, uint32& r1, uint32 addr) {
    asm volatile("ldmatrix.sync.aligned.m8n8.x2.shared.b16 {%0,%1}, [%2];"
        : "=r"(r0), "=r"(r1) : "r"(addr));
}
__device__ __forceinline__ void cp16(uint32 dst, const float* src) {
    asm volatile("cp.async.ca.shared.global [%0], [%1], 16;" :: "r"(dst), "l"(src));
}
#define CP_COMMIT() asm volatile("cp.async.commit_group;")
#define CP_WAIT2()  asm volatile("cp.async.wait_group 2;")
#define CP_WAIT1()  asm volatile("cp.async.wait_group 1;")
#define CP_WAIT0()  asm volatile("cp.async.wait_group 0;")

// ---------------- kernel 0: rna tf32 pre-rounding of x and all weights ----------------
__global__ __launch_bounds__(256) void round_kernel(
    const float* __restrict__ x,
    const float* __restrict__ Wq, const float* __restrict__ Wk,
    const float* __restrict__ Wv, const float* __restrict__ Wu,
    const float* __restrict__ Wf)
{
    const int b = blockIdx.x, t = threadIdx.x;
    const float* src; float* dst; int i4;
    if (b < 1024)      { src = x;  dst = g_xr;          i4 = b*256 + t; }
    else if (b < 1040) { src = Wq; dst = g_wr;          i4 = (b-1024)*256 + t; }
    else if (b < 1056) { src = Wk; dst = g_wr + 16384;  i4 = (b-1040)*256 + t; }
    else if (b < 1072) { src = Wv; dst = g_wr + 32768;  i4 = (b-1056)*256 + t; }
    else if (b < 1104) { src = Wu; dst = g_wr + 49152;  i4 = (b-1072)*256 + t; }
    else               { src = Wf; dst = g_wf;          i4 = (b-1104)*256 + t; }
    float4 v = ((const float4*)src)[i4];
    ((float4*)dst)[i4] = make_float4(tf32f(v.x), tf32f(v.y), tf32f(v.z), tf32f(v.w));
}

// ---------------- kernel 1: fused q/k/v/u projections (tf32 mma, cp.async pipeline) ----------------
#define PROJ_SMEM 53248
__global__ __launch_bounds__(256) void proj_kernel(
    const float* __restrict__ bq, const float* __restrict__ bk,
    const float* __restrict__ bv, const float* __restrict__ bu)
{
    extern __shared__ float psm[];
    float (*xs)[36]  = (float(*)[36])psm;                 // 2 x 64 rows
    float (*ws)[136] = (float(*)[136])(psm + 2*64*36);    // 2 x 32 rows

    const int seg = blockIdx.x;
    const int r0  = blockIdx.y * 64;

    const float* W; const float* bias; int ldw, c0;
    if (seg == 0)      { W = g_wr;         bias = bq; ldw = 128; c0 = 0; }
    else if (seg == 1) { W = g_wr + 16384; bias = bk; ldw = 128; c0 = 0; }
    else if (seg == 2) { W = g_wr + 32768; bias = bv; ldw = 128; c0 = 0; }
    else               { W = g_wr + 49152; bias = bu; ldw = 256; c0 = (seg - 3) * 128; }

    const int t = threadIdx.x;
    const int w = t >> 5, lane = t & 31;
    const int wm = w & 3, wn = w >> 2;
    const int g = lane >> 2, tg = lane & 3;

    const int lrow = lane & 7;
    const int sel4 = lane >> 3;
    const int a_ro = ((sel4 & 1) << 3) + lrow;
    const int a_co = (sel4 & 2) ? 4 : 0;

    const uint32 xs_u = smem_u32(&xs[0][0]);
    const uint32 ws_u = smem_u32(&ws[0][0]);
    const float* xp = g_xr + r0 * 128;

    #pragma unroll
    for (int i = t; i < 512; i += 256) {
        int r = i >> 3, q = (i & 7) << 2;
        cp16(xs_u + (r*36 + q)*4, xp + r*128 + q);
    }
    #pragma unroll
    for (int i = t; i < 1024; i += 256) {
        int r = i >> 5, q = (i & 31) << 2;
        cp16(ws_u + (r*136 + q)*4, W + r*ldw + c0 + q);
    }
    CP_COMMIT();

    float4 acc[8];
    #pragma unroll
    for (int j = 0; j < 8; j++) acc[j] = make_float4(0.f, 0.f, 0.f, 0.f);

    const uint32 xa = xs_u + ((wm*16 + a_ro)*36 + a_co)*4;

    #pragma unroll
    for (int kc = 0; kc < 4; kc++) {
        const int buf = kc & 1;
        if (kc < 3) {
            const int nb = buf ^ 1, k1 = (kc + 1) * 32;
            #pragma unroll
            for (int i = t; i < 512; i += 256) {
                int r = i >> 3, q = (i & 7) << 2;
                cp16(xs_u + ((nb*64 + r)*36 + q)*4, xp + r*128 + k1 + q);
            }
            #pragma unroll
            for (int i = t; i < 1024; i += 256) {
                int r = i >> 5, q = (i & 31) << 2;
                cp16(ws_u + ((nb*32 + r)*136 + q)*4, W + (k1 + r)*ldw + c0 + q);
            }
            CP_COMMIT();
            CP_WAIT1();
        } else {
            CP_WAIT0();
        }
        __syncthreads();

        const uint32 xab = xa + (uint32)buf*64*36*4;
        #pragma unroll
        for (int kk = 0; kk < 32; kk += 8) {
            uint32 A[4];
            ldsm_x4(A[0], A[1], A[2], A[3], xab + kk*4);
            #pragma unroll
            for (int j = 0; j < 8; j++) {
                uint32 b0 = fb(ws[buf*32 + kk + tg    ][wn*64 + j*8 + g]);
                uint32 b1 = fb(ws[buf*32 + kk + tg + 4][wn*64 + j*8 + g]);
                mma_tf32(acc[j], A[0], A[1], A[2], A[3], b0, b1);
            }
        }
        __syncthreads();
    }

    if (seg == 2) {
        const int bb = r0 >> 11;
        const int tok = (r0 & 2047) + wm*16 + g;
        #pragma unroll
        for (int j = 0; j < 8; j++) {
            int col = wn*64 + j*8 + 2*tg;
            float b0v = bias[col], b1v = bias[col + 1];
            float v00 = tf32f(silu_f(acc[j].x + b0v));
            float v01 = tf32f(silu_f(acc[j].y + b1v));
            float v10 = tf32f(silu_f(acc[j].z + b0v));
            float v11 = tf32f(silu_f(acc[j].w + b1v));
            float* p0 = &g_vt[(bb*128 + col) * SEQ + tok];
            p0[0] = v00; p0[8] = v10;
            float* p1 = p0 + SEQ;
            p1[0] = v01; p1[8] = v11;
        }
    } else {
        float* out = (seg == 0) ? g_q : (seg == 1) ? g_k : g_u;
        bool act = (seg <= 1);
        const float mult = (seg == 0) ? 0.17677669529663687f : 1.0f;
        #pragma unroll
        for (int j = 0; j < 8; j++) {
            int col = c0 + wn*64 + j*8 + 2*tg;
            float b0v = bias[col], b1v = bias[col + 1];
            int row0 = r0 + wm*16 + g;
            float v00 = acc[j].x + b0v, v01 = acc[j].y + b1v;
            float v10 = acc[j].z + b0v, v11 = acc[j].w + b1v;
            if (act) {
                v00 = tf32f(silu_f(v00) * mult); v01 = tf32f(silu_f(v01) * mult);
                v10 = tf32f(silu_f(v10) * mult); v11 = tf32f(silu_f(v11) * mult);
            }
            *(float2*)&out[row0 * ldw + col]       = make_float2(v00, v01);
            *(float2*)&out[(row0 + 8) * ldw + col] = make_float2(v10, v11);
        }
    }
}

// ---------------- kernel 2: MERGED attn + pos (proven R11 structure) ----------------
// grid 512, 256 threads, 62464 B dyn smem, 2 CTA/SM. Even blocks = attn, odd = pos.
#define AP_SMEM 62464

__device__ __forceinline__ void attn_body(int p, int bh, int t, float* sm)
{
    float (*qs)[36]  = (float(*)[36])sm;                 // 64 rows
    float (*ks)[36]  = (float(*)[36])(sm + 2304);        // 2*64 rows
    float (*vts)[68] = (float(*)[68])(sm + 6912);        // 2*32 rows
    float (*ss)[68]  = (float(*)[68])(sm + 11264);       // 64 rows

    const int b = bh >> 2, h = bh & 3;
    const int w = t >> 5, lane = t & 31;
    const int wm = w & 3, wn = w >> 2;
    const int g = lane >> 2, tg = lane & 3;

    const float* kp  = g_k  + (b*SEQ)*128 + h*32;
    const float* vtp = g_vt + (b*128 + h*32)*SEQ;

    const uint32 qs_u = smem_u32(&qs[0][0]);
    const uint32 ks_u = smem_u32(&ks[0][0]);
    const uint32 vt_u = smem_u32(&vts[0][0]);
    const uint32 ss_u = smem_u32(&ss[0][0]);

    const int lrow = lane & 7;
    const int sel4 = lane >> 3;
    const int a_ro = ((sel4 & 1) << 3) + lrow;
    const int a_co = (sel4 & 2) ? 4 : 0;
    const int l16  = lane & 15;
    const int b_ro = l16 & 7;
    const int b_co = (l16 >> 3) << 2;

    const uint32 qa = qs_u + ((wm*16 + a_ro)*36 + a_co)*4;
    const uint32 sa = ss_u + ((wm*16 + a_ro)*68 + a_co)*4;

    #pragma unroll
    for (int ph = 0; ph < 2; ph++) {
        const int tile = ph ? p : 31 - p;        // long phase first
        const int n0 = tile * 64;
        const float* qp = g_q + (b*SEQ + n0)*128 + h*32;

        #pragma unroll
        for (int c = t; c < 512; c += 256) {
            int r = c >> 3, s = (c & 7) << 2;
            cp16(qs_u + (r*36 + s)*4, qp + r*128 + s);
        }
        #pragma unroll
        for (int c = t; c < 512; c += 256) {
            int r = c >> 3, s = (c & 7) << 2;
            cp16(ks_u + (r*36 + s)*4, kp + r*128 + s);
        }
        #pragma unroll
        for (int c = t; c < 512; c += 256) {
            int r = c >> 4, s = (c & 15) << 2;
            cp16(vt_u + (r*68 + s)*4, vtp + r*SEQ + s);
        }
        CP_COMMIT();

        float4 acc2[2];
        acc2[0] = make_float4(0.f, 0.f, 0.f, 0.f);
        acc2[1] = make_float4(0.f, 0.f, 0.f, 0.f);

        const int iters = tile + 1;
        for (int it = 0; it < iters; ++it) {
            const int m0 = it * 64;
            const int buf = it & 1;
            if (it + 1 < iters) {
                const int m1 = m0 + 64, nb = buf ^ 1;
                #pragma unroll
                for (int c = t; c < 512; c += 256) {
                    int r = c >> 3, s = (c & 7) << 2;
                    cp16(ks_u + ((nb*64 + r)*36 + s)*4, kp + (m1 + r)*128 + s);
                }
                #pragma unroll
                for (int c = t; c < 512; c += 256) {
                    int r = c >> 4, s = (c & 15) << 2;
                    cp16(vt_u + ((nb*32 + r)*68 + s)*4, vtp + r*SEQ + m1 + s);
                }
                CP_COMMIT();
                CP_WAIT1();
            } else {
                CP_WAIT0();
            }
            __syncthreads();

            // stage 1: scores 64x64 (warp m16 x n32)
            float4 sc[4];
            #pragma unroll
            for (int j = 0; j < 4; j++) sc[j] = make_float4(0.f, 0.f, 0.f, 0.f);

            const uint32 kb = ks_u + (uint32)buf*64*36*4 + ((wn*32 + b_ro)*36 + b_co)*4;
            #pragma unroll
            for (int kk = 0; kk < 32; kk += 8) {
                uint32 A[4];
                ldsm_x4(A[0], A[1], A[2], A[3], qa + kk*4);
                #pragma unroll
                for (int j = 0; j < 4; j++) {
                    uint32 b0, b1;
                    ldsm_x2(b0, b1, kb + (j*8*36 + kk)*4);
                    mma_tf32(sc[j], A[0], A[1], A[2], A[3], b0, b1);
                }
            }

            // mask + square + silu(tanh) -> ss (tf32)
            {
                const int lr = wm*16 + g;
                const int nrow0 = n0 + lr, nrow1 = nrow0 + 8;
                #pragma unroll
                for (int j = 0; j < 4; j++) {
                    const int lc = wn*32 + j*8 + 2*tg;
                    const int cc = m0 + lc;
                    float s;
                    s = sc[j].x; s = (cc     <= nrow0) ? s*s : 0.f; float w00 = tf32f(silu_t(s));
                    s = sc[j].y; s = (cc + 1 <= nrow0) ? s*s : 0.f; float w01 = tf32f(silu_t(s));
                    s = sc[j].z; s = (cc     <= nrow1) ? s*s : 0.f; float w10 = tf32f(silu_t(s));
                    s = sc[j].w; s = (cc + 1 <= nrow1) ? s*s : 0.f; float w11 = tf32f(silu_t(s));
                    *(float2*)&ss[lr    ][lc] = make_float2(w00, w01);
                    *(float2*)&ss[lr + 8][lc] = make_float2(w10, w11);
                }
            }
            __syncthreads();

            // stage 2: acc2 += ss @ v  (warp m16 x d16)
            const uint32 vb = vt_u + (uint32)buf*32*68*4 + ((wn*16 + b_ro)*68 + b_co)*4;
            #pragma unroll
            for (int kk = 0; kk < 64; kk += 8) {
                uint32 A[4];
                ldsm_x4(A[0], A[1], A[2], A[3], sa + kk*4);
                #pragma unroll
                for (int j = 0; j < 2; j++) {
                    uint32 b0, b1;
                    ldsm_x2(b0, b1, vb + (j*8*68 + kk)*4);
                    mma_tf32(acc2[j], A[0], A[1], A[2], A[3], b0, b1);
                }
            }
            __syncthreads();
        }

        {
            const int row0 = n0 + wm*16 + g;
            #pragma unroll
            for (int j = 0; j < 2; j++) {
                const int col = h*32 + wn*16 + j*8 + 2*tg;
                *(float2*)&g_sattn[(b*SEQ + row0    )*128 + col] = make_float2(acc2[j].x, acc2[j].y);
                *(float2*)&g_sattn[(b*SEQ + row0 + 8)*128 + col] = make_float2(acc2[j].z, acc2[j].w);
            }
        }
    }
}

__device__ __forceinline__ void pos_body(int idx, int t, float* sm, const float* __restrict__ pos_w)
{
    float* swl = sm;                                   // 4096 (tf32-rounded pos_w)
    float (*vts)[68] = (float(*)[68])(sm + 4096);      // 2*64 rows

    const int n0 = (idx & 31) * 64;
    const int d0 = ((idx >> 5) & 1) * 64;
    const int b  = idx >> 6;
    const int w = t >> 5, lane = t & 31;
    const int wmn = w & 1, wd = w >> 1;
    const int g = lane >> 2, tg = lane & 3;

    const int l16  = lane & 15;
    const int b_ro = l16 & 7;
    const int b_co = (l16 >> 3) << 2;

    const uint32 vt_u = smem_u32(&vts[0][0]);
    const float* vtp = g_vt + (b*128 + d0)*SEQ;

    for (int i = t; i < 4095; i += 256) swl[i] = tf32f(pos_w[i]);
    if (t == 0) swl[4095] = 0.f;

    #pragma unroll
    for (int c = t; c < 1024; c += 256) {
        int r = c >> 4, s = (c & 15) << 2;
        cp16(vt_u + (r*68 + s)*4, vtp + r*SEQ + s);
    }
    CP_COMMIT();

    float4 acc[2][2];
    #pragma unroll
    for (int mi = 0; mi < 2; mi++)
        #pragma unroll
        for (int j = 0; j < 2; j++) acc[mi][j] = make_float4(0.f, 0.f, 0.f, 0.f);

    const int abase = 2047 - n0 - wmn*32 - g + tg;

    for (int it = 0; it < 32; ++it) {
        const int m0 = it * 64;
        const int buf = it & 1;
        if (it < 31) {
            const int m1 = m0 + 64, nb = buf ^ 1;
            #pragma unroll
            for (int c = t; c < 1024; c += 256) {
                int r = c >> 4, s = (c & 15) << 2;
                cp16(vt_u + ((nb*64 + r)*68 + s)*4, vtp + r*SEQ + m1 + s);
            }
            CP_COMMIT();
            CP_WAIT1();
        } else {
            CP_WAIT0();
        }
        __syncthreads();

        const uint32 vb = vt_u + (uint32)buf*64*68*4 + ((wd*16 + b_ro)*68 + b_co)*4;
        const float* ab = swl + abase + m0;
        #pragma unroll
        for (int kk = 0; kk < 64; kk += 8) {
            uint32 A0[4], A1[4];
            {
                const float* pp = ab + kk;
                A0[0] = fb(pp[0]);   A0[1] = fb(pp[-8]);
                A0[2] = fb(pp[4]);   A0[3] = fb(pp[-4]);
                const float* qq = pp - 16;
                A1[0] = fb(qq[0]);   A1[1] = fb(qq[-8]);
                A1[2] = fb(qq[4]);   A1[3] = fb(qq[-4]);
            }
            #pragma unroll
            for (int j = 0; j < 2; j++) {
                uint32 b0, b1;
                ldsm_x2(b0, b1, vb + (j*8*68 + kk)*4);
                mma_tf32(acc[0][j], A0[0], A0[1], A0[2], A0[3], b0, b1);
                mma_tf32(acc[1][j], A1[0], A1[1], A1[2], A1[3], b0, b1);
            }
        }
        __syncthreads();
    }

    #pragma unroll
    for (int mi = 0; mi < 2; mi++) {
        const int row0 = n0 + wmn*32 + mi*16 + g;
        #pragma unroll
        for (int j = 0; j < 2; j++) {
            const int col = d0 + wd*16 + j*8 + 2*tg;
            *(float2*)&g_pattn[(b*SEQ + row0    )*128 + col] = make_float2(acc[mi][j].x, acc[mi][j].y);
            *(float2*)&g_pattn[(b*SEQ + row0 + 8)*128 + col] = make_float2(acc[mi][j].z, acc[mi][j].w);
        }
    }
}

__global__ __launch_bounds__(256, 2) void attnpos_kernel(const float* __restrict__ pos_w)
{
    extern __shared__ float sm[];
    const int bx = blockIdx.x;
    const int idx = bx >> 1;
    if ((bx & 1) == 0) {
        attn_body(idx & 15, idx >> 4, threadIdx.x, sm);
    } else {
        pos_body(idx, threadIdx.x, sm, pos_w);
    }
}

// ---------------- kernel 3: fused LN + final GEMM, split over N ----------------
// grid (256, 2), 256 threads. Block: 32 rows x 64 cols. LN duplicated per column half.
// smem: as[32][260] (33280 B) + ws[2][32][68] (17408 B) = 50688 B
#define FIN_SMEM 50688
__global__ __launch_bounds__(256) void final_kernel(const float* __restrict__ x,
                                                    const float* __restrict__ bf,
                                                    const float* __restrict__ gamma,
                                                    const float* __restrict__ beta,
                                                    float* __restrict__ out)
{
    extern __shared__ float sm[];
    float (*as)[260] = (float(*)[260])sm;            // 32 rows, cols 0..255 = [sattn|pattn]
    float (*ws)[68]  = (float(*)[68])(sm + 32*260);  // 2 x 32 rows x 64 cols

    const int r0 = blockIdx.x * 32;
    const int c0 = blockIdx.y * 64;
    const int t  = threadIdx.x;
    const uint32 as_u = smem_u32(&as[0][0]);
    const uint32 ws_u = smem_u32(&ws[0][0]);

    // group 0: activations (32 rows x 256 floats = 2048 float4)
    #pragma unroll
    for (int i = t; i < 2048; i += 256) {
        int r = i >> 6, c4 = i & 63;
        const float* src = (c4 < 32) ? &g_sattn[(r0 + r)*128 + c4*4]
                                     : &g_pattn[(r0 + r)*128 + (c4 - 32)*4];
        cp16(as_u + (r*260 + c4*4)*4, src);
    }
    CP_COMMIT();
    // groups 1,2: Wf chunks 0,1 (each 32 rows x 64 floats = 512 float4 -> 2/thread)
    #pragma unroll
    for (int i = t; i < 512; i += 256) {
        int r = i >> 4, c4 = i & 15;
        cp16(ws_u + (r*68 + c4*4)*4, &g_wf[r*128 + c0 + c4*4]);
    }
    CP_COMMIT();
    #pragma unroll
    for (int i = t; i < 512; i += 256) {
        int r = i >> 4, c4 = i & 15;
        cp16(ws_u + ((32 + r)*68 + c4*4)*4, &g_wf[(32 + r)*128 + c0 + c4*4]);
    }
    CP_COMMIT();
    CP_WAIT2();   // activations ready
    __syncthreads();

    // ---- LayerNorm: 8 threads/row; thread covers cols {sub*4 + k4*32}
    {
        const int r = t >> 3, sub = t & 7;
        float vals[32];
        #pragma unroll
        for (int k4 = 0; k4 < 8; k4++) {
            float4 v = *(const float4*)&as[r][sub*4 + k4*32];
            vals[k4*4+0] = v.x; vals[k4*4+1] = v.y; vals[k4*4+2] = v.z; vals[k4*4+3] = v.w;
        }
        float sum = 0.f, sq = 0.f;
        #pragma unroll
        for (int k = 0; k < 32; k++) { sum += vals[k]; sq = fmaf(vals[k], vals[k], sq); }
        #pragma unroll
        for (int o = 1; o < 8; o <<= 1) {
            sum += __shfl_xor_sync(0xffffffffu, sum, o);
            sq  += __shfl_xor_sync(0xffffffffu, sq, o);
        }
        const float mean = sum * (1.f / 256.f);
        const float var  = sq * (1.f / 256.f) - mean * mean;
        const float rstd = rsqrtf(var + 1e-3f);

        #pragma unroll
        for (int k4 = 0; k4 < 8; k4++) {
            const int c = sub*4 + k4*32;
            float4 ga = *(const float4*)&gamma[c];
            float4 be = *(const float4*)&beta[c];
            float4 uu = *(const float4*)&g_u[(r0 + r)*256 + c];
            float4 o;
            o.x = tf32f(uu.x * ((vals[k4*4+0] - mean) * rstd * ga.x + be.x));
            o.y = tf32f(uu.y * ((vals[k4*4+1] - mean) * rstd * ga.y + be.y));
            o.z = tf32f(uu.z * ((vals[k4*4+2] - mean) * rstd * ga.z + be.z));
            o.w = tf32f(uu.w * ((vals[k4*4+3] - mean) * rstd * ga.w + be.w));
            *(float4*)&as[r][c] = o;
        }
    }
    __syncthreads();

    // ---- GEMM 32x256 @ Wf[256, c0:c0+64] via tf32 MMA, double-buffered ----
    const int w = t >> 5, lane = t & 31;
    const int wm = w & 1, wn = w >> 1;         // 2m x 4n (warp m16 x n16)
    const int g = lane >> 2, tg = lane & 3;
    const int lrow = lane & 7;
    const int sel4 = lane >> 3;
    const int a_ro = ((sel4 & 1) << 3) + lrow;
    const int a_co = (sel4 & 2) ? 4 : 0;

    const uint32 aa = as_u + ((wm*16 + a_ro)*260 + a_co)*4;

    float4 acc[2];
    acc[0] = make_float4(0.f, 0.f, 0.f, 0.f);
    acc[1] = make_float4(0.f, 0.f, 0.f, 0.f);

    #pragma unroll
    for (int kchunk = 0; kchunk < 8; kchunk++) {
        const int buf = kchunk & 1;
        CP_WAIT1();
        __syncthreads();

        #pragma unroll
        for (int kk = 0; kk < 32; kk += 8) {
            uint32 A[4];
            ldsm_x4(A[0], A[1], A[2], A[3], aa + (kchunk*32 + kk)*4);
            #pragma unroll
            for (int j = 0; j < 2; j++) {
                uint32 b0 = fb(ws[buf*32 + kk + tg    ][wn*16 + j*8 + g]);
                uint32 b1 = fb(ws[buf*32 + kk + tg + 4][wn*16 + j*8 + g]);
                mma_tf32(acc[j], A[0], A[1], A[2], A[3], b0, b1);
            }
        }
        __syncthreads();

        if (kchunk + 2 < 8) {
            #pragma unroll
            for (int i = t; i < 512; i += 256) {
                int r = i >> 4, c4 = i & 15;
                cp16(ws_u + ((buf*32 + r)*68 + c4*4)*4,
                     &g_wf[((kchunk + 2)*32 + r)*128 + c0 + c4*4]);
            }
        }
        CP_COMMIT();
    }

    // epilogue: +bf, relu, +x
    {
        const int row0 = r0 + wm*16 + g, row1 = row0 + 8;
        #pragma unroll
        for (int j = 0; j < 2; j++) {
            const int col = c0 + wn*16 + j*8 + 2*tg;
            float b0v = bf[col], b1v = bf[col + 1];
            float2 x0 = *(const float2*)&x[row0*128 + col];
            float2 x1 = *(const float2*)&x[row1*128 + col];
            float2 o0, o1;
            o0.x = fmaxf(acc[j].x + b0v, 0.f) + x0.x;
            o0.y = fmaxf(acc[j].y + b1v, 0.f) + x0.y;
            o1.x = fmaxf(acc[j].z + b0v, 0.f) + x1.x;
            o1.y = fmaxf(acc[j].w + b1v, 0.f) + x1.y;
            *(float2*)&out[row0*128 + col] = o0;
            *(float2*)&out[row1*128 + col] = o1;
        }
    }
}

// ---------------- launcher ----------------
extern "C" void kernel_launch(void* const* d_in, const int* in_sizes, int n_in,
                              void* d_out, int out_size)
{
    const float* x      = (const float*)d_in[0];
    const float* Wq     = (const float*)d_in[1];
    const float* bq     = (const float*)d_in[2];
    const float* Wk     = (const float*)d_in[3];
    const float* bk     = (const float*)d_in[4];
    const float* Wv     = (const float*)d_in[5];
    const float* bv     = (const float*)d_in[6];
    const float* Wu     = (const float*)d_in[7];
    const float* bu     = (const float*)d_in[8];
    const float* pos_w  = (const float*)d_in[9];
    const float* gamma  = (const float*)d_in[10];
    const float* beta   = (const float*)d_in[11];
    const float* Wf     = (const float*)d_in[12];
    const float* bf     = (const float*)d_in[13];
    float* out = (float*)d_out;

    cudaFuncSetAttribute(proj_kernel,    cudaFuncAttributeMaxDynamicSharedMemorySize, PROJ_SMEM);
    cudaFuncSetAttribute(attnpos_kernel, cudaFuncAttributeMaxDynamicSharedMemorySize, AP_SMEM);
    cudaFuncSetAttribute(final_kernel,   cudaFuncAttributeMaxDynamicSharedMemorySize, FIN_SMEM);

    round_kernel<<<1136, 256>>>(x, Wq, Wk, Wv, Wu, Wf);
    proj_kernel<<<dim3(5, ROWS/64), 256, PROJ_SMEM>>>(bq, bk, bv, bu);
    attnpos_kernel<<<512, 256, AP_SMEM>>>(pos_w);
    final_kernel<<<dim3(ROWS/32, 2), 256, FIN_SMEM>>>(x, bf, gamma, beta, out);
}

// round 14
// speedup vs baseline: 1.1802x; 1.0559x over previous
#include <cuda_runtime.h>
#include <math.h>

#define BATCH 4
#define SEQ   2048
#define DIM   128
#define ROWS  (BATCH*SEQ)   // 8192

typedef unsigned long long ull;
typedef unsigned int uint32;

// ---------------- scratch (no allocation allowed) ----------------
__device__ float g_xr[ROWS*DIM];           // rna tf32-rounded x
__device__ float g_wr[DIM*(3*DIM+2*DIM)];  // rna tf32 Wq|Wk|Wv|Wu
__device__ float g_q[ROWS*DIM];            // tf32, PRE-SCALED by 1/sqrt(32)
__device__ float g_k[ROWS*DIM];
__device__ float g_vt[ROWS*DIM];           // TRANSPOSED: [b][d=128][token=2048]
__device__ float g_u[ROWS*2*DIM];          // full f32
__device__ float g_wf[2*DIM*DIM];          // rna tf32 Wf
__device__ float g_sattn[ROWS*DIM];
__device__ float g_pattn[ROWS*DIM];

__device__ __forceinline__ float silu_f(float v) {
    return v * (1.f / (1.f + __expf(-v)));
}
__device__ __forceinline__ float tanh_ap(float x) {
    float y; asm("tanh.approx.f32 %0, %1;" : "=f"(y) : "f"(x)); return y;
}
__device__ __forceinline__ float silu_t(float x) {
    return fmaf(x, 0.5f * tanh_ap(0.5f * x), 0.5f * x);
}
__device__ __forceinline__ uint32 tf32_of(float f) {
    uint32 u; asm("cvt.rna.tf32.f32 %0, %1;" : "=r"(u) : "f"(f)); return u;
}
__device__ __forceinline__ float tf32f(float f) { return __uint_as_float(tf32_of(f)); }
__device__ __forceinline__ uint32 fb(float f) { return __float_as_uint(f); }
__device__ __forceinline__ uint32 smem_u32(const void* p) {
    return (uint32)__cvta_generic_to_shared(p);
}

__device__ __forceinline__ void mma_tf32(float4& d, uint32 a0, uint32 a1, uint32 a2, uint32 a3,
                                         uint32 b0, uint32 b1) {
    asm volatile(
        "mma.sync.aligned.m16n8k8.row.col.f32.tf32.tf32.f32 "
        "{%0,%1,%2,%3}, {%4,%5,%6,%7}, {%8,%9}, {%0,%1,%2,%3};"
        : "+f"(d.x), "+f"(d.y), "+f"(d.z), "+f"(d.w)
        : "r"(a0), "r"(a1), "r"(a2), "r"(a3), "r"(b0), "r"(b1));
}
__device__ __forceinline__ void ldsm_x4(uint32& r0, uint32& r1, uint32& r2, uint32& r3, uint32 addr) {
    asm volatile("ldmatrix.sync.aligned.m8n8.x4.shared.b16 {%0,%1,%2,%3}, [%4];"
        : "=r"(r0), "=r"(r1), "=r"(r2), "=r"(r3) : "r"(addr));
}
__device__ __forceinline__ void ldsm_x2(uint32& r0, uint32& r1, uint32 addr) {
    asm volatile("ldmatrix.sync.aligned.m8n8.x2.shared.b16 {%0,%1}, [%2];"
        : "=r"(r0), "=r"(r1) : "r"(addr));
}
__device__ __forceinline__ void cp16(uint32 dst, const float* src) {
    asm volatile("cp.async.ca.shared.global [%0], [%1], 16;" :: "r"(dst), "l"(src));
}
#define CP_COMMIT() asm volatile("cp.async.commit_group;")
#define CP_WAIT2()  asm volatile("cp.async.wait_group 2;")
#define CP_WAIT1()  asm volatile("cp.async.wait_group 1;")
#define CP_WAIT0()  asm volatile("cp.async.wait_group 0;")

// ---------------- kernel 0: rna tf32 pre-rounding of x and all weights ----------------
__global__ __launch_bounds__(256) void round_kernel(
    const float* __restrict__ x,
    const float* __restrict__ Wq, const float* __restrict__ Wk,
    const float* __restrict__ Wv, const float* __restrict__ Wu,
    const float* __restrict__ Wf)
{
    const int b = blockIdx.x, t = threadIdx.x;
    const float* src; float* dst; int i4;
    if (b < 1024)      { src = x;  dst = g_xr;          i4 = b*256 + t; }
    else if (b < 1040) { src = Wq; dst = g_wr;          i4 = (b-1024)*256 + t; }
    else if (b < 1056) { src = Wk; dst = g_wr + 16384;  i4 = (b-1040)*256 + t; }
    else if (b < 1072) { src = Wv; dst = g_wr + 32768;  i4 = (b-1056)*256 + t; }
    else if (b < 1104) { src = Wu; dst = g_wr + 49152;  i4 = (b-1072)*256 + t; }
    else               { src = Wf; dst = g_wf;          i4 = (b-1104)*256 + t; }
    float4 v = ((const float4*)src)[i4];
    ((float4*)dst)[i4] = make_float4(tf32f(v.x), tf32f(v.y), tf32f(v.z), tf32f(v.w));
}

// ---------------- kernel 1: fused q/k/v/u projections (tf32 mma, cp.async pipeline) ----------------
#define PROJ_SMEM 53248
__global__ __launch_bounds__(256) void proj_kernel(
    const float* __restrict__ bq, const float* __restrict__ bk,
    const float* __restrict__ bv, const float* __restrict__ bu)
{
    extern __shared__ float psm[];
    float (*xs)[36]  = (float(*)[36])psm;                 // 2 x 64 rows
    float (*ws)[136] = (float(*)[136])(psm + 2*64*36);    // 2 x 32 rows

    const int seg = blockIdx.x;
    const int r0  = blockIdx.y * 64;

    const float* W; const float* bias; int ldw, c0;
    if (seg == 0)      { W = g_wr;         bias = bq; ldw = 128; c0 = 0; }
    else if (seg == 1) { W = g_wr + 16384; bias = bk; ldw = 128; c0 = 0; }
    else if (seg == 2) { W = g_wr + 32768; bias = bv; ldw = 128; c0 = 0; }
    else               { W = g_wr + 49152; bias = bu; ldw = 256; c0 = (seg - 3) * 128; }

    const int t = threadIdx.x;
    const int w = t >> 5, lane = t & 31;
    const int wm = w & 3, wn = w >> 2;
    const int g = lane >> 2, tg = lane & 3;

    const int lrow = lane & 7;
    const int sel4 = lane >> 3;
    const int a_ro = ((sel4 & 1) << 3) + lrow;
    const int a_co = (sel4 & 2) ? 4 : 0;

    const uint32 xs_u = smem_u32(&xs[0][0]);
    const uint32 ws_u = smem_u32(&ws[0][0]);
    const float* xp = g_xr + r0 * 128;

    #pragma unroll
    for (int i = t; i < 512; i += 256) {
        int r = i >> 3, q = (i & 7) << 2;
        cp16(xs_u + (r*36 + q)*4, xp + r*128 + q);
    }
    #pragma unroll
    for (int i = t; i < 1024; i += 256) {
        int r = i >> 5, q = (i & 31) << 2;
        cp16(ws_u + (r*136 + q)*4, W + r*ldw + c0 + q);
    }
    CP_COMMIT();

    float4 acc[8];
    #pragma unroll
    for (int j = 0; j < 8; j++) acc[j] = make_float4(0.f, 0.f, 0.f, 0.f);

    const uint32 xa = xs_u + ((wm*16 + a_ro)*36 + a_co)*4;

    #pragma unroll
    for (int kc = 0; kc < 4; kc++) {
        const int buf = kc & 1;
        if (kc < 3) {
            const int nb = buf ^ 1, k1 = (kc + 1) * 32;
            #pragma unroll
            for (int i = t; i < 512; i += 256) {
                int r = i >> 3, q = (i & 7) << 2;
                cp16(xs_u + ((nb*64 + r)*36 + q)*4, xp + r*128 + k1 + q);
            }
            #pragma unroll
            for (int i = t; i < 1024; i += 256) {
                int r = i >> 5, q = (i & 31) << 2;
                cp16(ws_u + ((nb*32 + r)*136 + q)*4, W + (k1 + r)*ldw + c0 + q);
            }
            CP_COMMIT();
            CP_WAIT1();
        } else {
            CP_WAIT0();
        }
        __syncthreads();

        const uint32 xab = xa + (uint32)buf*64*36*4;
        #pragma unroll
        for (int kk = 0; kk < 32; kk += 8) {
            uint32 A[4];
            ldsm_x4(A[0], A[1], A[2], A[3], xab + kk*4);
            #pragma unroll
            for (int j = 0; j < 8; j++) {
                uint32 b0 = fb(ws[buf*32 + kk + tg    ][wn*64 + j*8 + g]);
                uint32 b1 = fb(ws[buf*32 + kk + tg + 4][wn*64 + j*8 + g]);
                mma_tf32(acc[j], A[0], A[1], A[2], A[3], b0, b1);
            }
        }
        __syncthreads();
    }

    if (seg == 2) {
        const int bb = r0 >> 11;
        const int tok = (r0 & 2047) + wm*16 + g;
        #pragma unroll
        for (int j = 0; j < 8; j++) {
            int col = wn*64 + j*8 + 2*tg;
            float b0v = bias[col], b1v = bias[col + 1];
            float v00 = tf32f(silu_f(acc[j].x + b0v));
            float v01 = tf32f(silu_f(acc[j].y + b1v));
            float v10 = tf32f(silu_f(acc[j].z + b0v));
            float v11 = tf32f(silu_f(acc[j].w + b1v));
            float* p0 = &g_vt[(bb*128 + col) * SEQ + tok];
            p0[0] = v00; p0[8] = v10;
            float* p1 = p0 + SEQ;
            p1[0] = v01; p1[8] = v11;
        }
    } else {
        float* out = (seg == 0) ? g_q : (seg == 1) ? g_k : g_u;
        bool act = (seg <= 1);
        const float mult = (seg == 0) ? 0.17677669529663687f : 1.0f;
        #pragma unroll
        for (int j = 0; j < 8; j++) {
            int col = c0 + wn*64 + j*8 + 2*tg;
            float b0v = bias[col], b1v = bias[col + 1];
            int row0 = r0 + wm*16 + g;
            float v00 = acc[j].x + b0v, v01 = acc[j].y + b1v;
            float v10 = acc[j].z + b0v, v11 = acc[j].w + b1v;
            if (act) {
                v00 = tf32f(silu_f(v00) * mult); v01 = tf32f(silu_f(v01) * mult);
                v10 = tf32f(silu_f(v10) * mult); v11 = tf32f(silu_f(v11) * mult);
            }
            *(float2*)&out[row0 * ldw + col]       = make_float2(v00, v01);
            *(float2*)&out[(row0 + 8) * ldw + col] = make_float2(v10, v11);
        }
    }
}

// ---------------- kernel 2: MERGED attn + pos, 3 CTAs/SM (single-ish wave) ----------------
// grid 512, 256 threads, 62464 B dyn smem (3 x 62464 = 187392 B/SM fits).
#define AP_SMEM 62464

__device__ __forceinline__ void attn_body(int p, int bh, int t, float* sm)
{
    float (*qs)[36]  = (float(*)[36])sm;                 // 64 rows
    float (*ks)[36]  = (float(*)[36])(sm + 2304);        // 2*64 rows
    float (*vts)[68] = (float(*)[68])(sm + 6912);        // 2*32 rows
    float (*ss)[68]  = (float(*)[68])(sm + 11264);       // 64 rows

    const int b = bh >> 2, h = bh & 3;
    const int w = t >> 5, lane = t & 31;
    const int wm = w & 3, wn = w >> 2;
    const int g = lane >> 2, tg = lane & 3;

    const float* kp  = g_k  + (b*SEQ)*128 + h*32;
    const float* vtp = g_vt + (b*128 + h*32)*SEQ;

    const uint32 qs_u = smem_u32(&qs[0][0]);
    const uint32 ks_u = smem_u32(&ks[0][0]);
    const uint32 vt_u = smem_u32(&vts[0][0]);
    const uint32 ss_u = smem_u32(&ss[0][0]);

    const int lrow = lane & 7;
    const int sel4 = lane >> 3;
    const int a_ro = ((sel4 & 1) << 3) + lrow;
    const int a_co = (sel4 & 2) ? 4 : 0;
    const int l16  = lane & 15;
    const int b_ro = l16 & 7;
    const int b_co = (l16 >> 3) << 2;

    const uint32 qa = qs_u + ((wm*16 + a_ro)*36 + a_co)*4;
    const uint32 sa = ss_u + ((wm*16 + a_ro)*68 + a_co)*4;

    #pragma unroll
    for (int ph = 0; ph < 2; ph++) {
        const int tile = ph ? p : 31 - p;        // long phase first
        const int n0 = tile * 64;
        const float* qp = g_q + (b*SEQ + n0)*128 + h*32;

        #pragma unroll
        for (int c = t; c < 512; c += 256) {
            int r = c >> 3, s = (c & 7) << 2;
            cp16(qs_u + (r*36 + s)*4, qp + r*128 + s);
        }
        #pragma unroll
        for (int c = t; c < 512; c += 256) {
            int r = c >> 3, s = (c & 7) << 2;
            cp16(ks_u + (r*36 + s)*4, kp + r*128 + s);
        }
        #pragma unroll
        for (int c = t; c < 512; c += 256) {
            int r = c >> 4, s = (c & 15) << 2;
            cp16(vt_u + (r*68 + s)*4, vtp + r*SEQ + s);
        }
        CP_COMMIT();

        float4 acc2[2];
        acc2[0] = make_float4(0.f, 0.f, 0.f, 0.f);
        acc2[1] = make_float4(0.f, 0.f, 0.f, 0.f);

        const int iters = tile + 1;
        for (int it = 0; it < iters; ++it) {
            const int m0 = it * 64;
            const int buf = it & 1;
            if (it + 1 < iters) {
                const int m1 = m0 + 64, nb = buf ^ 1;
                #pragma unroll
                for (int c = t; c < 512; c += 256) {
                    int r = c >> 3, s = (c & 7) << 2;
                    cp16(ks_u + ((nb*64 + r)*36 + s)*4, kp + (m1 + r)*128 + s);
                }
                #pragma unroll
                for (int c = t; c < 512; c += 256) {
                    int r = c >> 4, s = (c & 15) << 2;
                    cp16(vt_u + ((nb*32 + r)*68 + s)*4, vtp + r*SEQ + m1 + s);
                }
                CP_COMMIT();
                CP_WAIT1();
            } else {
                CP_WAIT0();
            }
            __syncthreads();

            // stage 1: scores 64x64 (warp m16 x n32)
            float4 sc[4];
            #pragma unroll
            for (int j = 0; j < 4; j++) sc[j] = make_float4(0.f, 0.f, 0.f, 0.f);

            const uint32 kb = ks_u + (uint32)buf*64*36*4 + ((wn*32 + b_ro)*36 + b_co)*4;
            #pragma unroll
            for (int kk = 0; kk < 32; kk += 8) {
                uint32 A[4];
                ldsm_x4(A[0], A[1], A[2], A[3], qa + kk*4);
                #pragma unroll
                for (int j = 0; j < 4; j++) {
                    uint32 b0, b1;
                    ldsm_x2(b0, b1, kb + (j*8*36 + kk)*4);
                    mma_tf32(sc[j], A[0], A[1], A[2], A[3], b0, b1);
                }
            }

            // mask + square + silu(tanh) -> ss (tf32)
            {
                const int lr = wm*16 + g;
                const int nrow0 = n0 + lr, nrow1 = nrow0 + 8;
                #pragma unroll
                for (int j = 0; j < 4; j++) {
                    const int lc = wn*32 + j*8 + 2*tg;
                    const int cc = m0 + lc;
                    float s;
                    s = sc[j].x; s = (cc     <= nrow0) ? s*s : 0.f; float w00 = tf32f(silu_t(s));
                    s = sc[j].y; s = (cc + 1 <= nrow0) ? s*s : 0.f; float w01 = tf32f(silu_t(s));
                    s = sc[j].z; s = (cc     <= nrow1) ? s*s : 0.f; float w10 = tf32f(silu_t(s));
                    s = sc[j].w; s = (cc + 1 <= nrow1) ? s*s : 0.f; float w11 = tf32f(silu_t(s));
                    *(float2*)&ss[lr    ][lc] = make_float2(w00, w01);
                    *(float2*)&ss[lr + 8][lc] = make_float2(w10, w11);
                }
            }
            __syncthreads();

            // stage 2: acc2 += ss @ v  (warp m16 x d16)
            const uint32 vb = vt_u + (uint32)buf*32*68*4 + ((wn*16 + b_ro)*68 + b_co)*4;
            #pragma unroll
            for (int kk = 0; kk < 64; kk += 8) {
                uint32 A[4];
                ldsm_x4(A[0], A[1], A[2], A[3], sa + kk*4);
                #pragma unroll
                for (int j = 0; j < 2; j++) {
                    uint32 b0, b1;
                    ldsm_x2(b0, b1, vb + (j*8*68 + kk)*4);
                    mma_tf32(acc2[j], A[0], A[1], A[2], A[3], b0, b1);
                }
            }
            __syncthreads();
        }

        {
            const int row0 = n0 + wm*16 + g;
            #pragma unroll
            for (int j = 0; j < 2; j++) {
                const int col = h*32 + wn*16 + j*8 + 2*tg;
                *(float2*)&g_sattn[(b*SEQ + row0    )*128 + col] = make_float2(acc2[j].x, acc2[j].y);
                *(float2*)&g_sattn[(b*SEQ + row0 + 8)*128 + col] = make_float2(acc2[j].z, acc2[j].w);
            }
        }
    }
}

__device__ __forceinline__ void pos_body(int idx, int t, float* sm, const float* __restrict__ pos_w)
{
    float* swl = sm;                                   // 4096 (tf32-rounded pos_w)
    float (*vts)[68] = (float(*)[68])(sm + 4096);      // 2*64 rows

    const int n0 = (idx & 31) * 64;
    const int d0 = ((idx >> 5) & 1) * 64;
    const int b  = idx >> 6;
    const int w = t >> 5, lane = t & 31;
    const int wmn = w & 1, wd = w >> 1;
    const int g = lane >> 2, tg = lane & 3;

    const int l16  = lane & 15;
    const int b_ro = l16 & 7;
    const int b_co = (l16 >> 3) << 2;

    const uint32 vt_u = smem_u32(&vts[0][0]);
    const float* vtp = g_vt + (b*128 + d0)*SEQ;

    for (int i = t; i < 4095; i += 256) swl[i] = tf32f(pos_w[i]);
    if (t == 0) swl[4095] = 0.f;

    #pragma unroll
    for (int c = t; c < 1024; c += 256) {
        int r = c >> 4, s = (c & 15) << 2;
        cp16(vt_u + (r*68 + s)*4, vtp + r*SEQ + s);
    }
    CP_COMMIT();

    float4 acc[2][2];
    #pragma unroll
    for (int mi = 0; mi < 2; mi++)
        #pragma unroll
        for (int j = 0; j < 2; j++) acc[mi][j] = make_float4(0.f, 0.f, 0.f, 0.f);

    const int abase = 2047 - n0 - wmn*32 - g + tg;

    for (int it = 0; it < 32; ++it) {
        const int m0 = it * 64;
        const int buf = it & 1;
        if (it < 31) {
            const int m1 = m0 + 64, nb = buf ^ 1;
            #pragma unroll
            for (int c = t; c < 1024; c += 256) {
                int r = c >> 4, s = (c & 15) << 2;
                cp16(vt_u + ((nb*64 + r)*68 + s)*4, vtp + r*SEQ + m1 + s);
            }
            CP_COMMIT();
            CP_WAIT1();
        } else {
            CP_WAIT0();
        }
        __syncthreads();

        const uint32 vb = vt_u + (uint32)buf*64*68*4 + ((wd*16 + b_ro)*68 + b_co)*4;
        const float* ab = swl + abase + m0;
        #pragma unroll
        for (int kk = 0; kk < 64; kk += 8) {
            uint32 A0[4], A1[4];
            {
                const float* pp = ab + kk;
                A0[0] = fb(pp[0]);   A0[1] = fb(pp[-8]);
                A0[2] = fb(pp[4]);   A0[3] = fb(pp[-4]);
                const float* qq = pp - 16;
                A1[0] = fb(qq[0]);   A1[1] = fb(qq[-8]);
                A1[2] = fb(qq[4]);   A1[3] = fb(qq[-4]);
            }
            #pragma unroll
            for (int j = 0; j < 2; j++) {
                uint32 b0, b1;
                ldsm_x2(b0, b1, vb + (j*8*68 + kk)*4);
                mma_tf32(acc[0][j], A0[0], A0[1], A0[2], A0[3], b0, b1);
                mma_tf32(acc[1][j], A1[0], A1[1], A1[2], A1[3], b0, b1);
            }
        }
        __syncthreads();
    }

    #pragma unroll
    for (int mi = 0; mi < 2; mi++) {
        const int row0 = n0 + wmn*32 + mi*16 + g;
        #pragma unroll
        for (int j = 0; j < 2; j++) {
            const int col = d0 + wd*16 + j*8 + 2*tg;
            *(float2*)&g_pattn[(b*SEQ + row0    )*128 + col] = make_float2(acc[mi][j].x, acc[mi][j].y);
            *(float2*)&g_pattn[(b*SEQ + row0 + 8)*128 + col] = make_float2(acc[mi][j].z, acc[mi][j].w);
        }
    }
}

__global__ __launch_bounds__(256, 3) void attnpos_kernel(const float* __restrict__ pos_w)
{
    extern __shared__ float sm[];
    const int bx = blockIdx.x;
    const int idx = bx >> 1;
    if ((bx & 1) == 0) {
        attn_body(idx & 15, idx >> 4, threadIdx.x, sm);
    } else {
        pos_body(idx, threadIdx.x, sm, pos_w);
    }
}

// ---------------- kernel 3: fused LN + final GEMM (grid 256, proven 18.2us version) ----------------
#define FIN_SMEM 67072
__global__ __launch_bounds__(256) void final_kernel(const float* __restrict__ x,
                                                    const float* __restrict__ bf,
                                                    const float* __restrict__ gamma,
                                                    const float* __restrict__ beta,
                                                    float* __restrict__ out)
{
    extern __shared__ float sm[];
    float (*as)[260] = (float(*)[260])sm;
    float (*ws)[132] = (float(*)[132])(sm + 32*260);

    const int r0 = blockIdx.x * 32;
    const int t  = threadIdx.x;
    const uint32 as_u = smem_u32(&as[0][0]);
    const uint32 ws_u = smem_u32(&ws[0][0]);

    #pragma unroll
    for (int i = t; i < 2048; i += 256) {
        int r = i >> 6, c4 = i & 63;
        const float* src = (c4 < 32) ? &g_sattn[(r0 + r)*128 + c4*4]
                                     : &g_pattn[(r0 + r)*128 + (c4 - 32)*4];
        cp16(as_u + (r*260 + c4*4)*4, src);
    }
    CP_COMMIT();
    #pragma unroll
    for (int i = t; i < 1024; i += 256) {
        int r = i >> 5, c4 = i & 31;
        cp16(ws_u + (r*132 + c4*4)*4, &g_wf[r*128 + c4*4]);
    }
    CP_COMMIT();
    #pragma unroll
    for (int i = t; i < 1024; i += 256) {
        int r = i >> 5, c4 = i & 31;
        cp16(ws_u + ((32 + r)*132 + c4*4)*4, &g_wf[(32 + r)*128 + c4*4]);
    }
    CP_COMMIT();
    CP_WAIT2();
    __syncthreads();

    {
        const int r = t >> 3, sub = t & 7;
        float vals[32];
        #pragma unroll
        for (int k4 = 0; k4 < 8; k4++) {
            float4 v = *(const float4*)&as[r][sub*4 + k4*32];
            vals[k4*4+0] = v.x; vals[k4*4+1] = v.y; vals[k4*4+2] = v.z; vals[k4*4+3] = v.w;
        }
        float sum = 0.f, sq = 0.f;
        #pragma unroll
        for (int k = 0; k < 32; k++) { sum += vals[k]; sq = fmaf(vals[k], vals[k], sq); }
        #pragma unroll
        for (int o = 1; o < 8; o <<= 1) {
            sum += __shfl_xor_sync(0xffffffffu, sum, o);
            sq  += __shfl_xor_sync(0xffffffffu, sq, o);
        }
        const float mean = sum * (1.f / 256.f);
        const float var  = sq * (1.f / 256.f) - mean * mean;
        const float rstd = rsqrtf(var + 1e-3f);

        #pragma unroll
        for (int k4 = 0; k4 < 8; k4++) {
            const int c = sub*4 + k4*32;
            float4 ga = *(const float4*)&gamma[c];
            float4 be = *(const float4*)&beta[c];
            float4 uu = *(const float4*)&g_u[(r0 + r)*256 + c];
            float4 o;
            o.x = tf32f(uu.x * ((vals[k4*4+0] - mean) * rstd * ga.x + be.x));
            o.y = tf32f(uu.y * ((vals[k4*4+1] - mean) * rstd * ga.y + be.y));
            o.z = tf32f(uu.z * ((vals[k4*4+2] - mean) * rstd * ga.z + be.z));
            o.w = tf32f(uu.w * ((vals[k4*4+3] - mean) * rstd * ga.w + be.w));
            *(float4*)&as[r][c] = o;
        }
    }
    __syncthreads();

    const int w = t >> 5, lane = t & 31;
    const int wm = w & 1, wn = w >> 1;
    const int g = lane >> 2, tg = lane & 3;
    const int lrow = lane & 7;
    const int sel4 = lane >> 3;
    const int a_ro = ((sel4 & 1) << 3) + lrow;
    const int a_co = (sel4 & 2) ? 4 : 0;

    const uint32 aa = as_u + ((wm*16 + a_ro)*260 + a_co)*4;

    float4 acc[4];
    #pragma unroll
    for (int j = 0; j < 4; j++) acc[j] = make_float4(0.f, 0.f, 0.f, 0.f);

    #pragma unroll
    for (int kchunk = 0; kchunk < 8; kchunk++) {
        const int buf = kchunk & 1;
        CP_WAIT1();
        __syncthreads();

        #pragma unroll
        for (int kk = 0; kk < 32; kk += 8) {
            uint32 A[4];
            ldsm_x4(A[0], A[1], A[2], A[3], aa + (kchunk*32 + kk)*4);
            #pragma unroll
            for (int j = 0; j < 4; j++) {
                uint32 b0 = fb(ws[buf*32 + kk + tg    ][wn*32 + j*8 + g]);
                uint32 b1 = fb(ws[buf*32 + kk + tg + 4][wn*32 + j*8 + g]);
                mma_tf32(acc[j], A[0], A[1], A[2], A[3], b0, b1);
            }
        }
        __syncthreads();

        if (kchunk + 2 < 8) {
            #pragma unroll
            for (int i = t; i < 1024; i += 256) {
                int r = i >> 5, c4 = i & 31;
                cp16(ws_u + ((buf*32 + r)*132 + c4*4)*4,
                     &g_wf[((kchunk + 2)*32 + r)*128 + c4*4]);
            }
        }
        CP_COMMIT();
    }

    {
        const int row0 = r0 + wm*16 + g, row1 = row0 + 8;
        #pragma unroll
        for (int j = 0; j < 4; j++) {
            const int col = wn*32 + j*8 + 2*tg;
            float b0v = bf[col], b1v = bf[col + 1];
            float2 x0 = *(const float2*)&x[row0*128 + col];
            float2 x1 = *(const float2*)&x[row1*128 + col];
            float2 o0, o1;
            o0.x = fmaxf(acc[j].x + b0v, 0.f) + x0.x;
            o0.y = fmaxf(acc[j].y + b1v, 0.f) + x0.y;
            o1.x = fmaxf(acc[j].z + b0v, 0.f) + x1.x;
            o1.y = fmaxf(acc[j].w + b1v, 0.f) + x1.y;
            *(float2*)&out[row0*128 + col] = o0;
            *(float2*)&out[row1*128 + col] = o1;
        }
    }
}

// ---------------- launcher ----------------
extern "C" void kernel_launch(void* const* d_in, const int* in_sizes, int n_in,
                              void* d_out, int out_size)
{
    const float* x      = (const float*)d_in[0];
    const float* Wq     = (const float*)d_in[1];
    const float* bq     = (const float*)d_in[2];
    const float* Wk     = (const float*)d_in[3];
    const float* bk     = (const float*)d_in[4];
    const float* Wv     = (const float*)d_in[5];
    const float* bv     = (const float*)d_in[6];
    const float* Wu     = (const float*)d_in[7];
    const float* bu     = (const float*)d_in[8];
    const float* pos_w  = (const float*)d_in[9];
    const float* gamma  = (const float*)d_in[10];
    const float* beta   = (const float*)d_in[11];
    const float* Wf     = (const float*)d_in[12];
    const float* bf     = (const float*)d_in[13];
    float* out = (float*)d_out;

    cudaFuncSetAttribute(proj_kernel,    cudaFuncAttributeMaxDynamicSharedMemorySize, PROJ_SMEM);
    cudaFuncSetAttribute(attnpos_kernel, cudaFuncAttributeMaxDynamicSharedMemorySize, AP_SMEM);
    cudaFuncSetAttribute(final_kernel,   cudaFuncAttributeMaxDynamicSharedMemorySize, FIN_SMEM);

    round_kernel<<<1136, 256>>>(x, Wq, Wk, Wv, Wu, Wf);
    proj_kernel<<<dim3(5, ROWS/64), 256, PROJ_SMEM>>>(bq, bk, bv, bu);
    attnpos_kernel<<<512, 256, AP_SMEM>>>(pos_w);
    final_kernel<<<ROWS/32, 256, FIN_SMEM>>>(x, bf, gamma, beta, out);
}

// round 15
// speedup vs baseline: 1.4314x; 1.2129x over previous
#include <cuda_runtime.h>
#include <cuda_bf16.h>
#include <math.h>

#define BATCH 4
#define SEQ   2048
#define DIM   128
#define ROWS  (BATCH*SEQ)   // 8192

typedef unsigned long long ull;
typedef unsigned int uint32;

// ---------------- scratch (no allocation allowed) ----------------
__device__ float g_xr[ROWS*DIM];           // rna tf32-rounded x
__device__ float g_wr[DIM*(3*DIM+2*DIM)];  // rna tf32 Wq|Wk|Wv|Wu
__device__ float g_q[ROWS*DIM];            // tf32, PRE-SCALED by 1/sqrt(32)
__device__ float g_k[ROWS*DIM];
__device__ __nv_bfloat16 g_vt[ROWS*DIM];   // bf16, TRANSPOSED: [b][d=128][token=2048]
__device__ float g_u[ROWS*2*DIM];          // full f32
__device__ float g_wf[2*DIM*DIM];          // rna tf32 Wf
__device__ float g_sattn[ROWS*DIM];
__device__ float g_pattn[ROWS*DIM];

__device__ __forceinline__ float silu_f(float v) {
    return v * (1.f / (1.f + __expf(-v)));
}
__device__ __forceinline__ float tanh_ap(float x) {
    float y; asm("tanh.approx.f32 %0, %1;" : "=f"(y) : "f"(x)); return y;
}
__device__ __forceinline__ float silu_t(float x) {
    return fmaf(x, 0.5f * tanh_ap(0.5f * x), 0.5f * x);
}
__device__ __forceinline__ uint32 tf32_of(float f) {
    uint32 u; asm("cvt.rna.tf32.f32 %0, %1;" : "=r"(u) : "f"(f)); return u;
}
__device__ __forceinline__ float tf32f(float f) { return __uint_as_float(tf32_of(f)); }
__device__ __forceinline__ uint32 fb(float f) { return __float_as_uint(f); }
__device__ __forceinline__ uint32 bf2(float lo, float hi) {
    uint32 d; asm("cvt.rn.bf16x2.f32 %0, %1, %2;" : "=r"(d) : "f"(hi), "f"(lo)); return d;
}
__device__ __forceinline__ uint32 smem_u32(const void* p) {
    return (uint32)__cvta_generic_to_shared(p);
}

__device__ __forceinline__ void mma_tf32(float4& d, uint32 a0, uint32 a1, uint32 a2, uint32 a3,
                                         uint32 b0, uint32 b1) {
    asm volatile(
        "mma.sync.aligned.m16n8k8.row.col.f32.tf32.tf32.f32 "
        "{%0,%1,%2,%3}, {%4,%5,%6,%7}, {%8,%9}, {%0,%1,%2,%3};"
        : "+f"(d.x), "+f"(d.y), "+f"(d.z), "+f"(d.w)
        : "r"(a0), "r"(a1), "r"(a2), "r"(a3), "r"(b0), "r"(b1));
}
__device__ __forceinline__ void mma_bf16(float4& d, uint32 a0, uint32 a1, uint32 a2, uint32 a3,
                                         uint32 b0, uint32 b1) {
    asm volatile(
        "mma.sync.aligned.m16n8k16.row.col.f32.bf16.bf16.f32 "
        "{%0,%1,%2,%3}, {%4,%5,%6,%7}, {%8,%9}, {%0,%1,%2,%3};"
        : "+f"(d.x), "+f"(d.y), "+f"(d.z), "+f"(d.w)
        : "r"(a0), "r"(a1), "r"(a2), "r"(a3), "r"(b0), "r"(b1));
}
__device__ __forceinline__ void ldsm_x4(uint32& r0, uint32& r1, uint32& r2, uint32& r3, uint32 addr) {
    asm volatile("ldmatrix.sync.aligned.m8n8.x4.shared.b16 {%0,%1,%2,%3}, [%4];"
        : "=r"(r0), "=r"(r1), "=r"(r2), "=r"(r3) : "r"(addr));
}
__device__ __forceinline__ void ldsm_x2(uint32& r0, uint32& r1, uint32 addr) {
    asm volatile("ldmatrix.sync.aligned.m8n8.x2.shared.b16 {%0,%1}, [%2];"
        : "=r"(r0), "=r"(r1) : "r"(addr));
}
__device__ __forceinline__ void cp16(uint32 dst, const float* src) {
    asm volatile("cp.async.ca.shared.global [%0], [%1], 16;" :: "r"(dst), "l"(src));
}
#define CP_COMMIT() asm volatile("cp.async.commit_group;")
#define CP_WAIT2()  asm volatile("cp.async.wait_group 2;")
#define CP_WAIT1()  asm volatile("cp.async.wait_group 1;")
#define CP_WAIT0()  asm volatile("cp.async.wait_group 0;")

// ---------------- kernel 0: rna tf32 pre-rounding of x and all weights ----------------
__global__ __launch_bounds__(256) void round_kernel(
    const float* __restrict__ x,
    const float* __restrict__ Wq, const float* __restrict__ Wk,
    const float* __restrict__ Wv, const float* __restrict__ Wu,
    const float* __restrict__ Wf)
{
    const int b = blockIdx.x, t = threadIdx.x;
    const float* src; float* dst; int i4;
    if (b < 1024)      { src = x;  dst = g_xr;          i4 = b*256 + t; }
    else if (b < 1040) { src = Wq; dst = g_wr;          i4 = (b-1024)*256 + t; }
    else if (b < 1056) { src = Wk; dst = g_wr + 16384;  i4 = (b-1040)*256 + t; }
    else if (b < 1072) { src = Wv; dst = g_wr + 32768;  i4 = (b-1056)*256 + t; }
    else if (b < 1104) { src = Wu; dst = g_wr + 49152;  i4 = (b-1072)*256 + t; }
    else               { src = Wf; dst = g_wf;          i4 = (b-1104)*256 + t; }
    float4 v = ((const float4*)src)[i4];
    ((float4*)dst)[i4] = make_float4(tf32f(v.x), tf32f(v.y), tf32f(v.z), tf32f(v.w));
}

// ---------------- kernel 1: fused q/k/v/u projections (tf32 mma, cp.async pipeline) ----------------
#define PROJ_SMEM 53248
__global__ __launch_bounds__(256) void proj_kernel(
    const float* __restrict__ bq, const float* __restrict__ bk,
    const float* __restrict__ bv, const float* __restrict__ bu)
{
    extern __shared__ float psm[];
    float (*xs)[36]  = (float(*)[36])psm;                 // 2 x 64 rows
    float (*ws)[136] = (float(*)[136])(psm + 2*64*36);    // 2 x 32 rows

    const int seg = blockIdx.x;
    const int r0  = blockIdx.y * 64;

    const float* W; const float* bias; int ldw, c0;
    if (seg == 0)      { W = g_wr;         bias = bq; ldw = 128; c0 = 0; }
    else if (seg == 1) { W = g_wr + 16384; bias = bk; ldw = 128; c0 = 0; }
    else if (seg == 2) { W = g_wr + 32768; bias = bv; ldw = 128; c0 = 0; }
    else               { W = g_wr + 49152; bias = bu; ldw = 256; c0 = (seg - 3) * 128; }

    const int t = threadIdx.x;
    const int w = t >> 5, lane = t & 31;
    const int wm = w & 3, wn = w >> 2;
    const int g = lane >> 2, tg = lane & 3;

    const int lrow = lane & 7;
    const int sel4 = lane >> 3;
    const int a_ro = ((sel4 & 1) << 3) + lrow;
    const int a_co = (sel4 & 2) ? 4 : 0;

    const uint32 xs_u = smem_u32(&xs[0][0]);
    const uint32 ws_u = smem_u32(&ws[0][0]);
    const float* xp = g_xr + r0 * 128;

    #pragma unroll
    for (int i = t; i < 512; i += 256) {
        int r = i >> 3, q = (i & 7) << 2;
        cp16(xs_u + (r*36 + q)*4, xp + r*128 + q);
    }
    #pragma unroll
    for (int i = t; i < 1024; i += 256) {
        int r = i >> 5, q = (i & 31) << 2;
        cp16(ws_u + (r*136 + q)*4, W + r*ldw + c0 + q);
    }
    CP_COMMIT();

    float4 acc[8];
    #pragma unroll
    for (int j = 0; j < 8; j++) acc[j] = make_float4(0.f, 0.f, 0.f, 0.f);

    const uint32 xa = xs_u + ((wm*16 + a_ro)*36 + a_co)*4;

    #pragma unroll
    for (int kc = 0; kc < 4; kc++) {
        const int buf = kc & 1;
        if (kc < 3) {
            const int nb = buf ^ 1, k1 = (kc + 1) * 32;
            #pragma unroll
            for (int i = t; i < 512; i += 256) {
                int r = i >> 3, q = (i & 7) << 2;
                cp16(xs_u + ((nb*64 + r)*36 + q)*4, xp + r*128 + k1 + q);
            }
            #pragma unroll
            for (int i = t; i < 1024; i += 256) {
                int r = i >> 5, q = (i & 31) << 2;
                cp16(ws_u + ((nb*32 + r)*136 + q)*4, W + (k1 + r)*ldw + c0 + q);
            }
            CP_COMMIT();
            CP_WAIT1();
        } else {
            CP_WAIT0();
        }
        __syncthreads();

        const uint32 xab = xa + (uint32)buf*64*36*4;
        #pragma unroll
        for (int kk = 0; kk < 32; kk += 8) {
            uint32 A[4];
            ldsm_x4(A[0], A[1], A[2], A[3], xab + kk*4);
            #pragma unroll
            for (int j = 0; j < 8; j++) {
                uint32 b0 = fb(ws[buf*32 + kk + tg    ][wn*64 + j*8 + g]);
                uint32 b1 = fb(ws[buf*32 + kk + tg + 4][wn*64 + j*8 + g]);
                mma_tf32(acc[j], A[0], A[1], A[2], A[3], b0, b1);
            }
        }
        __syncthreads();
    }

    if (seg == 2) {
        // v: bf16 transposed store into g_vt[b][d][token]
        const int bb = r0 >> 11;
        const int tok = (r0 & 2047) + wm*16 + g;
        #pragma unroll
        for (int j = 0; j < 8; j++) {
            int col = wn*64 + j*8 + 2*tg;
            float b0v = bias[col], b1v = bias[col + 1];
            __nv_bfloat16* p0 = &g_vt[(bb*128 + col) * SEQ + tok];
            p0[0] = __float2bfloat16(silu_f(acc[j].x + b0v));
            p0[8] = __float2bfloat16(silu_f(acc[j].z + b0v));
            __nv_bfloat16* p1 = p0 + SEQ;
            p1[0] = __float2bfloat16(silu_f(acc[j].y + b1v));
            p1[8] = __float2bfloat16(silu_f(acc[j].w + b1v));
        }
    } else {
        float* out = (seg == 0) ? g_q : (seg == 1) ? g_k : g_u;
        bool act = (seg <= 1);
        const float mult = (seg == 0) ? 0.17677669529663687f : 1.0f;
        #pragma unroll
        for (int j = 0; j < 8; j++) {
            int col = c0 + wn*64 + j*8 + 2*tg;
            float b0v = bias[col], b1v = bias[col + 1];
            int row0 = r0 + wm*16 + g;
            float v00 = acc[j].x + b0v, v01 = acc[j].y + b1v;
            float v10 = acc[j].z + b0v, v11 = acc[j].w + b1v;
            if (act) {
                v00 = tf32f(silu_f(v00) * mult); v01 = tf32f(silu_f(v01) * mult);
                v10 = tf32f(silu_f(v10) * mult); v11 = tf32f(silu_f(v11) * mult);
            }
            *(float2*)&out[row0 * ldw + col]       = make_float2(v00, v01);
            *(float2*)&out[(row0 + 8) * ldw + col] = make_float2(v10, v11);
        }
    }
}

// ---------------- kernel 2: MERGED attn + pos (bf16 stage-2 / PV path) ----------------
// attn smem: qs 64x36 f32 (9216B) | ks 2x64x36 f32 (18432B) | vts 2x32x88 bf16 (11264B)
//            | ss 64x88 bf16 (11264B) = 50176 B
// pos smem:  swl 4096 f32 (16384B) | vts 2x64x88 bf16 (22528B) = 38912 B
#define AP_SMEM 50176

__device__ __forceinline__ void attn_body(int p, int bh, int t, float* sm)
{
    float (*qs)[36]  = (float(*)[36])sm;                   // 64 rows
    float (*ks)[36]  = (float(*)[36])(sm + 2304);          // 2*64 rows
    __nv_bfloat16* vtb = (__nv_bfloat16*)(sm + 6912);      // [2][32][88]
    __nv_bfloat16* ssb = (__nv_bfloat16*)(sm + 9728);      // [64][88]

    const int b = bh >> 2, h = bh & 3;
    const int w = t >> 5, lane = t & 31;
    const int wm = w & 3, wn = w >> 2;
    const int g = lane >> 2, tg = lane & 3;

    const float* kp = g_k + (b*SEQ)*128 + h*32;
    const __nv_bfloat16* vtp = g_vt + (b*128 + h*32)*SEQ;

    const uint32 qs_u = smem_u32(&qs[0][0]);
    const uint32 ks_u = smem_u32(&ks[0][0]);
    const uint32 vt_u = smem_u32(vtb);
    const uint32 ss_u = smem_u32(ssb);

    const int lrow = lane & 7;
    const int sel4 = lane >> 3;
    const int a_ro = ((sel4 & 1) << 3) + lrow;
    const int a_co = (sel4 & 2) ? 4 : 0;
    const int l16  = lane & 15;
    const int b_ro = l16 & 7;
    const int b_co = (l16 >> 3) << 2;

    const uint32 qa = qs_u + ((wm*16 + a_ro)*36 + a_co)*4;
    const uint32 sa = ss_u + (wm*16 + a_ro)*176 + ((sel4 & 2) ? 16 : 0);
    const uint32 vbw = vt_u + (wn*16 + b_ro)*176 + (l16 >> 3)*16;

    #pragma unroll
    for (int ph = 0; ph < 2; ph++) {
        const int tile = ph ? p : 31 - p;        // long phase first
        const int n0 = tile * 64;
        const float* qp = g_q + (b*SEQ + n0)*128 + h*32;

        #pragma unroll
        for (int c = t; c < 512; c += 256) {
            int r = c >> 3, s = (c & 7) << 2;
            cp16(qs_u + (r*36 + s)*4, qp + r*128 + s);
        }
        #pragma unroll
        for (int c = t; c < 512; c += 256) {
            int r = c >> 3, s = (c & 7) << 2;
            cp16(ks_u + (r*36 + s)*4, kp + r*128 + s);
        }
        {   // vt tile: 32 rows x 64 tok bf16 = 256 cp16 (1/thread)
            int r = t >> 3, c8 = t & 7;
            cp16(vt_u + r*176 + c8*16, (const float*)(vtp + r*SEQ + c8*8));
        }
        CP_COMMIT();

        float4 acc2[2];
        acc2[0] = make_float4(0.f, 0.f, 0.f, 0.f);
        acc2[1] = make_float4(0.f, 0.f, 0.f, 0.f);

        const int iters = tile + 1;
        for (int it = 0; it < iters; ++it) {
            const int m0 = it * 64;
            const int buf = it & 1;
            if (it + 1 < iters) {
                const int m1 = m0 + 64, nb = buf ^ 1;
                #pragma unroll
                for (int c = t; c < 512; c += 256) {
                    int r = c >> 3, s = (c & 7) << 2;
                    cp16(ks_u + ((nb*64 + r)*36 + s)*4, kp + (m1 + r)*128 + s);
                }
                {
                    int r = t >> 3, c8 = t & 7;
                    cp16(vt_u + (nb*32 + r)*176 + c8*16,
                         (const float*)(vtp + r*SEQ + m1 + c8*8));
                }
                CP_COMMIT();
                CP_WAIT1();
            } else {
                CP_WAIT0();
            }
            __syncthreads();

            // stage 1: scores 64x64 (warp m16 x n32), tf32
            float4 sc[4];
            #pragma unroll
            for (int j = 0; j < 4; j++) sc[j] = make_float4(0.f, 0.f, 0.f, 0.f);

            const uint32 kb = ks_u + (uint32)buf*64*36*4 + ((wn*32 + b_ro)*36 + b_co)*4;
            #pragma unroll
            for (int kk = 0; kk < 32; kk += 8) {
                uint32 A[4];
                ldsm_x4(A[0], A[1], A[2], A[3], qa + kk*4);
                #pragma unroll
                for (int j = 0; j < 4; j++) {
                    uint32 b0, b1;
                    ldsm_x2(b0, b1, kb + (j*8*36 + kk)*4);
                    mma_tf32(sc[j], A[0], A[1], A[2], A[3], b0, b1);
                }
            }

            // mask + square + silu(tanh) -> ss (bf16x2 packed stores)
            {
                const int lr = wm*16 + g;
                const int nrow0 = n0 + lr, nrow1 = nrow0 + 8;
                #pragma unroll
                for (int j = 0; j < 4; j++) {
                    const int lc = wn*32 + j*8 + 2*tg;
                    const int cc = m0 + lc;
                    float s;
                    s = sc[j].x; s = (cc     <= nrow0) ? s*s : 0.f; float w00 = silu_t(s);
                    s = sc[j].y; s = (cc + 1 <= nrow0) ? s*s : 0.f; float w01 = silu_t(s);
                    s = sc[j].z; s = (cc     <= nrow1) ? s*s : 0.f; float w10 = silu_t(s);
                    s = sc[j].w; s = (cc + 1 <= nrow1) ? s*s : 0.f; float w11 = silu_t(s);
                    *(uint32*)&ssb[lr*88 + lc]       = bf2(w00, w01);
                    *(uint32*)&ssb[(lr + 8)*88 + lc] = bf2(w10, w11);
                }
            }
            __syncthreads();

            // stage 2: acc2 += P @ V, bf16 m16n8k16 (warp m16 x d16)
            const uint32 vb = vbw + (uint32)buf*32*176;
            #pragma unroll
            for (int kk = 0; kk < 64; kk += 16) {
                uint32 A[4];
                ldsm_x4(A[0], A[1], A[2], A[3], sa + kk*2);
                #pragma unroll
                for (int j = 0; j < 2; j++) {
                    uint32 b0, b1;
                    ldsm_x2(b0, b1, vb + j*8*176 + kk*2);
                    mma_bf16(acc2[j], A[0], A[1], A[2], A[3], b0, b1);
                }
            }
            __syncthreads();
        }

        {
            const int row0 = n0 + wm*16 + g;
            #pragma unroll
            for (int j = 0; j < 2; j++) {
                const int col = h*32 + wn*16 + j*8 + 2*tg;
                *(float2*)&g_sattn[(b*SEQ + row0    )*128 + col] = make_float2(acc2[j].x, acc2[j].y);
                *(float2*)&g_sattn[(b*SEQ + row0 + 8)*128 + col] = make_float2(acc2[j].z, acc2[j].w);
            }
        }
    }
}

__device__ __forceinline__ void pos_body(int idx, int t, float* sm, const float* __restrict__ pos_w)
{
    float* swl = sm;                                   // 4096 f32
    __nv_bfloat16* vtb = (__nv_bfloat16*)(sm + 4096);  // [2][64][88]

    const int n0 = (idx & 31) * 64;
    const int d0 = ((idx >> 5) & 1) * 64;
    const int b  = idx >> 6;
    const int w = t >> 5, lane = t & 31;
    const int wmn = w & 1, wd = w >> 1;
    const int g = lane >> 2, tg = lane & 3;
    const int l16  = lane & 15;
    const int b_ro = l16 & 7;

    const uint32 vt_u = smem_u32(vtb);
    const __nv_bfloat16* vtp = g_vt + (b*128 + d0)*SEQ;

    for (int i = t; i < 4095; i += 256) swl[i] = pos_w[i];
    if (t == 0) swl[4095] = 0.f;

    // first vt tile: 64 rows x 64 tok bf16 = 512 cp16
    #pragma unroll
    for (int i = t; i < 512; i += 256) {
        int r = i >> 3, c8 = i & 7;
        cp16(vt_u + r*176 + c8*16, (const float*)(vtp + r*SEQ + c8*8));
    }
    CP_COMMIT();

    float4 acc[2][2];
    #pragma unroll
    for (int mi = 0; mi < 2; mi++)
        #pragma unroll
        for (int j = 0; j < 2; j++) acc[mi][j] = make_float4(0.f, 0.f, 0.f, 0.f);

    const uint32 vbw = vt_u + (wd*16 + b_ro)*176 + (l16 >> 3)*16;
    const int abase = 2047 - n0 - wmn*32 - g + 2*tg;

    for (int it = 0; it < 32; ++it) {
        const int m0 = it * 64;
        const int buf = it & 1;
        if (it < 31) {
            const int m1 = m0 + 64, nb = buf ^ 1;
            #pragma unroll
            for (int i = t; i < 512; i += 256) {
                int r = i >> 3, c8 = i & 7;
                cp16(vt_u + (nb*64 + r)*176 + c8*16,
                     (const float*)(vtp + r*SEQ + m1 + c8*8));
            }
            CP_COMMIT();
            CP_WAIT1();
        } else {
            CP_WAIT0();
        }
        __syncthreads();

        const uint32 vb = vbw + (uint32)buf*64*176;
        const float* ab2 = swl + abase + m0;
        #pragma unroll
        for (int kk = 0; kk < 64; kk += 16) {
            // Toeplitz A pairs (bf16x2): rows {g, g+8, g+16, g+24} x k-halves share values
            uint32 pP8  = bf2(ab2[kk + 8],  ab2[kk + 9]);
            uint32 p00  = bf2(ab2[kk],      ab2[kk + 1]);
            uint32 pM8  = bf2(ab2[kk - 8],  ab2[kk - 7]);
            uint32 pM16 = bf2(ab2[kk - 16], ab2[kk - 15]);
            uint32 pM24 = bf2(ab2[kk - 24], ab2[kk - 23]);
            #pragma unroll
            for (int j = 0; j < 2; j++) {
                uint32 b0, b1;
                ldsm_x2(b0, b1, vb + j*8*176 + kk*2);
                mma_bf16(acc[0][j], p00,  pM8,  pP8, p00,  b0, b1);
                mma_bf16(acc[1][j], pM16, pM24, pM8, pM16, b0, b1);
            }
        }
        __syncthreads();
    }

    #pragma unroll
    for (int mi = 0; mi < 2; mi++) {
        const int row0 = n0 + wmn*32 + mi*16 + g;
        #pragma unroll
        for (int j = 0; j < 2; j++) {
            const int col = d0 + wd*16 + j*8 + 2*tg;
            *(float2*)&g_pattn[(b*SEQ + row0    )*128 + col] = make_float2(acc[mi][j].x, acc[mi][j].y);
            *(float2*)&g_pattn[(b*SEQ + row0 + 8)*128 + col] = make_float2(acc[mi][j].z, acc[mi][j].w);
        }
    }
}

__global__ __launch_bounds__(256, 2) void attnpos_kernel(const float* __restrict__ pos_w)
{
    extern __shared__ float sm[];
    const int bx = blockIdx.x;
    const int idx = bx >> 1;
    if ((bx & 1) == 0) {
        attn_body(idx & 15, idx >> 4, threadIdx.x, sm);
    } else {
        pos_body(idx, threadIdx.x, sm, pos_w);
    }
}

// ---------------- kernel 3: fused LN + final GEMM (tf32 mma, pipelined Wf) ----------------
#define FIN_SMEM 67072
__global__ __launch_bounds__(256) void final_kernel(const float* __restrict__ x,
                                                    const float* __restrict__ bf,
                                                    const float* __restrict__ gamma,
                                                    const float* __restrict__ beta,
                                                    float* __restrict__ out)
{
    extern __shared__ float sm[];
    float (*as)[260] = (float(*)[260])sm;
    float (*ws)[132] = (float(*)[132])(sm + 32*260);

    const int r0 = blockIdx.x * 32;
    const int t  = threadIdx.x;
    const uint32 as_u = smem_u32(&as[0][0]);
    const uint32 ws_u = smem_u32(&ws[0][0]);

    #pragma unroll
    for (int i = t; i < 2048; i += 256) {
        int r = i >> 6, c4 = i & 63;
        const float* src = (c4 < 32) ? &g_sattn[(r0 + r)*128 + c4*4]
                                     : &g_pattn[(r0 + r)*128 + (c4 - 32)*4];
        cp16(as_u + (r*260 + c4*4)*4, src);
    }
    CP_COMMIT();
    #pragma unroll
    for (int i = t; i < 1024; i += 256) {
        int r = i >> 5, c4 = i & 31;
        cp16(ws_u + (r*132 + c4*4)*4, &g_wf[r*128 + c4*4]);
    }
    CP_COMMIT();
    #pragma unroll
    for (int i = t; i < 1024; i += 256) {
        int r = i >> 5, c4 = i & 31;
        cp16(ws_u + ((32 + r)*132 + c4*4)*4, &g_wf[(32 + r)*128 + c4*4]);
    }
    CP_COMMIT();
    CP_WAIT2();
    __syncthreads();

    {
        const int r = t >> 3, sub = t & 7;
        float vals[32];
        #pragma unroll
        for (int k4 = 0; k4 < 8; k4++) {
            float4 v = *(const float4*)&as[r][sub*4 + k4*32];
            vals[k4*4+0] = v.x; vals[k4*4+1] = v.y; vals[k4*4+2] = v.z; vals[k4*4+3] = v.w;
        }
        float sum = 0.f, sq = 0.f;
        #pragma unroll
        for (int k = 0; k < 32; k++) { sum += vals[k]; sq = fmaf(vals[k], vals[k], sq); }
        #pragma unroll
        for (int o = 1; o < 8; o <<= 1) {
            sum += __shfl_xor_sync(0xffffffffu, sum, o);
            sq  += __shfl_xor_sync(0xffffffffu, sq, o);
        }
        const float mean = sum * (1.f / 256.f);
        const float var  = sq * (1.f / 256.f) - mean * mean;
        const float rstd = rsqrtf(var + 1e-3f);

        #pragma unroll
        for (int k4 = 0; k4 < 8; k4++) {
            const int c = sub*4 + k4*32;
            float4 ga = *(const float4*)&gamma[c];
            float4 be = *(const float4*)&beta[c];
            float4 uu = *(const float4*)&g_u[(r0 + r)*256 + c];
            float4 o;
            o.x = tf32f(uu.x * ((vals[k4*4+0] - mean) * rstd * ga.x + be.x));
            o.y = tf32f(uu.y * ((vals[k4*4+1] - mean) * rstd * ga.y + be.y));
            o.z = tf32f(uu.z * ((vals[k4*4+2] - mean) * rstd * ga.z + be.z));
            o.w = tf32f(uu.w * ((vals[k4*4+3] - mean) * rstd * ga.w + be.w));
            *(float4*)&as[r][c] = o;
        }
    }
    __syncthreads();

    const int w = t >> 5, lane = t & 31;
    const int wm = w & 1, wn = w >> 1;
    const int g = lane >> 2, tg = lane & 3;
    const int lrow = lane & 7;
    const int sel4 = lane >> 3;
    const int a_ro = ((sel4 & 1) << 3) + lrow;
    const int a_co = (sel4 & 2) ? 4 : 0;

    const uint32 aa = as_u + ((wm*16 + a_ro)*260 + a_co)*4;

    float4 acc[4];
    #pragma unroll
    for (int j = 0; j < 4; j++) acc[j] = make_float4(0.f, 0.f, 0.f, 0.f);

    #pragma unroll
    for (int kchunk = 0; kchunk < 8; kchunk++) {
        const int buf = kchunk & 1;
        CP_WAIT1();
        __syncthreads();

        #pragma unroll
        for (int kk = 0; kk < 32; kk += 8) {
            uint32 A[4];
            ldsm_x4(A[0], A[1], A[2], A[3], aa + (kchunk*32 + kk)*4);
            #pragma unroll
            for (int j = 0; j < 4; j++) {
                uint32 b0 = fb(ws[buf*32 + kk + tg    ][wn*32 + j*8 + g]);
                uint32 b1 = fb(ws[buf*32 + kk + tg + 4][wn*32 + j*8 + g]);
                mma_tf32(acc[j], A[0], A[1], A[2], A[3], b0, b1);
            }
        }
        __syncthreads();

        if (kchunk + 2 < 8) {
            #pragma unroll
            for (int i = t; i < 1024; i += 256) {
                int r = i >> 5, c4 = i & 31;
                cp16(ws_u + ((buf*32 + r)*132 + c4*4)*4,
                     &g_wf[((kchunk + 2)*32 + r)*128 + c4*4]);
            }
        }
        CP_COMMIT();
    }

    {
        const int row0 = r0 + wm*16 + g, row1 = row0 + 8;
        #pragma unroll
        for (int j = 0; j < 4; j++) {
            const int col = wn*32 + j*8 + 2*tg;
            float b0v = bf[col], b1v = bf[col + 1];
            float2 x0 = *(const float2*)&x[row0*128 + col];
            float2 x1 = *(const float2*)&x[row1*128 + col];
            float2 o0, o1;
            o0.x = fmaxf(acc[j].x + b0v, 0.f) + x0.x;
            o0.y = fmaxf(acc[j].y + b1v, 0.f) + x0.y;
            o1.x = fmaxf(acc[j].z + b0v, 0.f) + x1.x;
            o1.y = fmaxf(acc[j].w + b1v, 0.f) + x1.y;
            *(float2*)&out[row0*128 + col] = o0;
            *(float2*)&out[row1*128 + col] = o1;
        }
    }
}

// ---------------- launcher ----------------
extern "C" void kernel_launch(void* const* d_in, const int* in_sizes, int n_in,
                              void* d_out, int out_size)
{
    const float* x      = (const float*)d_in[0];
    const float* Wq     = (const float*)d_in[1];
    const float* bq     = (const float*)d_in[2];
    const float* Wk     = (const float*)d_in[3];
    const float* bk     = (const float*)d_in[4];
    const float* Wv     = (const float*)d_in[5];
    const float* bv     = (const float*)d_in[6];
    const float* Wu     = (const float*)d_in[7];
    const float* bu     = (const float*)d_in[8];
    const float* pos_w  = (const float*)d_in[9];
    const float* gamma  = (const float*)d_in[10];
    const float* beta   = (const float*)d_in[11];
    const float* Wf     = (const float*)d_in[12];
    const float* bf     = (const float*)d_in[13];
    float* out = (float*)d_out;

    cudaFuncSetAttribute(proj_kernel,    cudaFuncAttributeMaxDynamicSharedMemorySize, PROJ_SMEM);
    cudaFuncSetAttribute(attnpos_kernel, cudaFuncAttributeMaxDynamicSharedMemorySize, AP_SMEM);
    cudaFuncSetAttribute(final_kernel,   cudaFuncAttributeMaxDynamicSharedMemorySize, FIN_SMEM);

    round_kernel<<<1136, 256>>>(x, Wq, Wk, Wv, Wu, Wf);
    proj_kernel<<<dim3(5, ROWS/64), 256, PROJ_SMEM>>>(bq, bk, bv, bu);
    attnpos_kernel<<<512, 256, AP_SMEM>>>(pos_w);
    final_kernel<<<ROWS/32, 256, FIN_SMEM>>>(x, bf, gamma, beta, out);
}